// round 14
// baseline (speedup 1.0000x reference)
#include <cuda_runtime.h>
#include <cuda_fp16.h>
#include <cstdint>

#define H 256

#define MAXV 100000
#define MAXE 150000
#define MAXL 80000
#define MAXF 60000
#define MAXPAIR 800000

#define OFF0 0
#define OFF1 (MAXE + 1)
#define OFF2 (MAXE + 1 + MAXL + 1)
#define CSRTOT (MAXE + MAXL + MAXF + 3)

// scratch (fp16 activations only)
__device__ __half   g_v16[(size_t)MAXV * H];   // vertex embed; reused as conv2-output
__device__ __half   g_e16[(size_t)MAXE * H];
__device__ __half   g_eo16[(size_t)MAXE * H];  // conv1 output
__device__ __half   g_l16[(size_t)MAXL * H];
__device__ __half   g_f16[(size_t)MAXF * H];
__device__ __half   g_wt16[3][512 * 256];      // transposed weights [256 n][512 k]
__device__ int      g_cnt[CSRTOT];
__device__ int      g_off[CSRTOT];
__device__ int      g_cur[CSRTOT];
__device__ int      g_col[MAXPAIR];
__device__ int      g_bsum[192];

// ---------- helpers ----------
__device__ __forceinline__ float leaky(float a) { return a >= 0.f ? a : 0.01f * a; }

__device__ __forceinline__ void mma_fp16(float c[4], const unsigned a[4], const unsigned b[2]) {
    asm volatile(
        "mma.sync.aligned.m16n8k16.row.col.f32.f16.f16.f32 "
        "{%0,%1,%2,%3},{%4,%5,%6,%7},{%8,%9},{%0,%1,%2,%3};"
        : "+f"(c[0]), "+f"(c[1]), "+f"(c[2]), "+f"(c[3])
        : "r"(a[0]), "r"(a[1]), "r"(a[2]), "r"(a[3]), "r"(b[0]), "r"(b[1]));
}

__device__ __forceinline__ void ldsm_x4(unsigned& r0, unsigned& r1, unsigned& r2, unsigned& r3,
                                        unsigned addr) {
    asm volatile("ldmatrix.sync.aligned.m8n8.x4.shared.b16 {%0,%1,%2,%3}, [%4];"
                 : "=r"(r0), "=r"(r1), "=r"(r2), "=r"(r3) : "r"(addr));
}

__device__ __forceinline__ void cp16(void* s, const void* g, bool valid) {
    unsigned saddr = (unsigned)__cvta_generic_to_shared(s);
    int sz = valid ? 16 : 0;
    asm volatile("cp.async.cg.shared.global [%0], [%1], 16, %2;" :: "r"(saddr), "l"(g), "r"(sz));
}
__device__ __forceinline__ void cp_commit() { asm volatile("cp.async.commit_group;"); }
template<int N> __device__ __forceinline__ void cp_wait() { asm volatile("cp.async.wait_group %0;" :: "n"(N)); }

// ---------- embedding body: fp16 output only ----------
template<int W0, int W1, int W2>
__device__ __forceinline__ void embed_body(int blk,
                                           const float* __restrict__ s0,
                                           const float* __restrict__ s1,
                                           const float* __restrict__ s2,
                                           const float* __restrict__ W,
                                           const float* __restrict__ bias,
                                           __half* __restrict__ out16, int n) {
    const int RB = 32;
    const int IN = W0 + W1 + W2;
    __shared__ float xs[RB][IN + 1];
    int row0 = blk * RB;
    int tid = threadIdx.x;
    int cg = tid & 63, rg = tid >> 6;

    for (int i = tid; i < RB * IN; i += 256) {
        int r = i / IN, k = i % IN;
        int row = row0 + r;
        float v = 0.f;
        if (row < n) {
            if (k < W0)            v = s0[(size_t)row * W0 + k];
            else if (k < W0 + W1)  v = s1[(size_t)row * W1 + (k - W0)];
            else                   v = s2[row];
        }
        xs[r][k] = v;
    }
    __syncthreads();

    float4 b = reinterpret_cast<const float4*>(bias)[cg];
    float4 acc[8];
#pragma unroll
    for (int q = 0; q < 8; q++) acc[q] = b;
#pragma unroll
    for (int k = 0; k < IN; k++) {
        float4 w = reinterpret_cast<const float4*>(W + (size_t)k * H)[cg];
#pragma unroll
        for (int q = 0; q < 8; q++) {
            float xv = xs[rg * 8 + q][k];
            acc[q].x += xv * w.x; acc[q].y += xv * w.y;
            acc[q].z += xv * w.z; acc[q].w += xv * w.w;
        }
    }
#pragma unroll
    for (int q = 0; q < 8; q++) {
        int row = row0 + rg * 8 + q;
        if (row < n) {
            uint2 o;
            __half2* oh = reinterpret_cast<__half2*>(&o);
            oh[0] = __floats2half2_rn(leaky(acc[q].x), leaky(acc[q].y));
            oh[1] = __floats2half2_rn(leaky(acc[q].z), leaky(acc[q].w));
            reinterpret_cast<uint2*>(out16 + (size_t)row * H)[cg] = o;
        }
    }
}

// all 4 embeddings in one launch
__global__ void embed_all(const float* __restrict__ vp,
                          const float* __restrict__ ec, const float* __restrict__ ecp,
                          const float* __restrict__ ecf,
                          const float* __restrict__ lt,
                          const float* __restrict__ fs, const float* __restrict__ fsp,
                          const float* __restrict__ fsf,
                          const float* __restrict__ Wv, const float* __restrict__ bv,
                          const float* __restrict__ We, const float* __restrict__ be,
                          const float* __restrict__ Wl, const float* __restrict__ bl,
                          const float* __restrict__ Wf, const float* __restrict__ bf,
                          __half* __restrict__ pv16, __half* __restrict__ pe16,
                          __half* __restrict__ pl16, __half* __restrict__ pf16,
                          int NVn, int NEn, int NLn, int NFn,
                          int nbv, int nbe, int nbl) {
    int b = blockIdx.x;
    if (b < nbv)                 embed_body<3, 0, 0>(b, vp, nullptr, nullptr, Wv, bv, pv16, NVn);
    else if (b < nbv + nbe)      embed_body<8, 6, 1>(b - nbv, ec, ecp, ecf, We, be, pe16, NEn);
    else if (b < nbv + nbe + nbl)embed_body<10, 0, 0>(b - nbv - nbe, lt, nullptr, nullptr, Wl, bl, pl16, NLn);
    else                         embed_body<12, 4, 1>(b - nbv - nbe - nbl, fs, fsp, fsf, Wf, bf, pf16, NFn);
}

// ---------- merged prep: weight transposes (blocks 0..383) + degree count (rest) ----------
__global__ void prep_kernel(const float* __restrict__ Wv0, const float* __restrict__ Wv1,
                            const float* __restrict__ Wv2, __half* __restrict__ Wt,
                            const int* __restrict__ d0, int n0,
                            const int* __restrict__ d1, int n1,
                            const int* __restrict__ d2, int n2,
                            int* __restrict__ cnt) {
    int b = blockIdx.x;
    if (b < 384) {
        __shared__ float tt[32][33];
        int z = b / 128, rem = b % 128;
        int bx = (rem & 15) * 32;   // k
        int by = (rem >> 4) * 32;   // n
        const float* W = (z == 0) ? Wv0 : (z == 1) ? Wv1 : Wv2;
        __half* O = Wt + (size_t)z * 512 * 256;
        int tx = threadIdx.x & 31, ty = threadIdx.x >> 5;  // 32 x 8
#pragma unroll
        for (int i = 0; i < 4; i++)
            tt[ty + i * 8][tx] = W[(size_t)(bx + ty + i * 8) * 256 + by + tx];
        __syncthreads();
#pragma unroll
        for (int i = 0; i < 4; i++)
            O[(size_t)(by + ty + i * 8) * 512 + bx + tx] = __float2half_rn(tt[tx][ty + i * 8]);
    } else {
        int i = (b - 384) * 256 + threadIdx.x;
        if (i < n0)                atomicAdd(&cnt[OFF0 + d0[i]], 1);
        else if (i < n0 + n1)      atomicAdd(&cnt[OFF1 + d1[i - n0]], 1);
        else if (i < n0 + n1 + n2) atomicAdd(&cnt[OFF2 + d2[i - n0 - n1]], 1);
    }
}

__global__ void scan_phase1(const int* __restrict__ cnt, int na, int nb_, int nc,
                            int* __restrict__ off, int* __restrict__ bsum) {
    __shared__ int wsum[32];
    int conv = blockIdx.y;
    int n = (conv == 0) ? na : (conv == 1) ? nb_ : nc;
    if (blockIdx.x * 4096 >= n) return;
    int base0 = (conv == 0) ? OFF0 : (conv == 1) ? OFF1 : OFF2;
    const int* c = cnt + base0;
    int* o = off + base0;
    int tid = threadIdx.x, lane = tid & 31, wid = tid >> 5;
    int base = blockIdx.x * 4096 + tid * 4;
    int v0 = (base     < n) ? c[base]     : 0;
    int v1 = (base + 1 < n) ? c[base + 1] : 0;
    int v2 = (base + 2 < n) ? c[base + 2] : 0;
    int v3 = (base + 3 < n) ? c[base + 3] : 0;
    int s = v0 + v1 + v2 + v3;
    int x = s;
#pragma unroll
    for (int d = 1; d < 32; d <<= 1) {
        int y = __shfl_up_sync(~0u, x, d);
        if (lane >= d) x += y;
    }
    if (lane == 31) wsum[wid] = x;
    __syncthreads();
    if (wid == 0) {
        int w = wsum[lane];
#pragma unroll
        for (int d = 1; d < 32; d <<= 1) {
            int y = __shfl_up_sync(~0u, w, d);
            if (lane >= d) w += y;
        }
        wsum[lane] = w;
    }
    __syncthreads();
    int run = x - s + (wid ? wsum[wid - 1] : 0);
    if (base     < n) o[base]     = run; run += v0;
    if (base + 1 < n) o[base + 1] = run; run += v1;
    if (base + 2 < n) o[base + 2] = run; run += v2;
    if (base + 3 < n) o[base + 3] = run;
    if (tid == 0) bsum[conv * 64 + blockIdx.x] = wsum[31];
}

__global__ void scan_phase2(int* __restrict__ bsum, int na, int nb_, int nc,
                            int* __restrict__ off) {
    __shared__ int tmp[64];
    int conv = blockIdx.x;
    int n = (conv == 0) ? na : (conv == 1) ? nb_ : nc;
    int base0 = (conv == 0) ? OFF0 : (conv == 1) ? OFF1 : OFF2;
    int* bs = bsum + conv * 64;
    int nb = (n + 4095) / 4096;
    int tid = threadIdx.x;
    int v = (tid < nb) ? bs[tid] : 0;
    tmp[tid] = v;
    __syncthreads();
    int x = v;
    for (int d = 1; d < 64; d <<= 1) {
        int y = (tid >= d) ? tmp[tid - d] : 0;
        __syncthreads();
        x += y;
        tmp[tid] = x;
        __syncthreads();
    }
    if (tid < nb) bs[tid] = x - v;
    if (tid == 63) off[base0 + n] = x;
}

__global__ void scan_phase3(int* __restrict__ off, const int* __restrict__ bsum,
                            int na, int nb_, int nc, int* __restrict__ cur) {
    int conv = blockIdx.y;
    int n = (conv == 0) ? na : (conv == 1) ? nb_ : nc;
    int i = blockIdx.x * blockDim.x + threadIdx.x;
    if (i >= n) return;
    int base0 = (conv == 0) ? OFF0 : (conv == 1) ? OFF1 : OFF2;
    int o = off[base0 + i] + bsum[conv * 64 + (i >> 12)];
    off[base0 + i] = o;
    cur[base0 + i] = o;
}

__global__ void fill_all_kernel(const int* __restrict__ e0, int n0,
                                const int* __restrict__ e1, int n1,
                                const int* __restrict__ e2, int n2,
                                int* __restrict__ cur, int* __restrict__ col) {
    int i = blockIdx.x * blockDim.x + threadIdx.x;
    const int* idx; int j, np, base0, cbase;
    if (i < n0)                { idx = e0; j = i;           np = n0; base0 = OFF0; cbase = 0; }
    else if (i < n0 + n1)      { idx = e1; j = i - n0;      np = n1; base0 = OFF1; cbase = n0; }
    else if (i < n0 + n1 + n2) { idx = e2; j = i - n0 - n1; np = n2; base0 = OFF2; cbase = n0 + n1; }
    else return;
    int d = idx[j];
    int s = idx[j + np];
    int pos = atomicAdd(&cur[base0 + d], 1);
    col[cbase + pos] = s;
}

// ---------- fused segmin + fp16 GEMM: 128x256 tile, 16 warps, 4-stage ----------
// iterations 0..7 consume x16 (staged); warp w computes segmin row w*8+it into
// smem mh buffer; iterations 8..15 read A fragments directly from mh buffer.
#define BM 128
#define BK 32
#define RSTR 20                     // stage row stride (words)
#define A_WORDS (128 * RSTR)        // 2560
#define B_WORDS (256 * RSTR)        // 5120
#define STG_WORDS (A_WORDS + B_WORDS)
#define STG_BYTES (STG_WORDS * 4)   // 30720
#define MH_STRIDE 132               // mh row stride in words (128 data + 4 pad)
#define MH_OFF_WORDS (4 * STG_WORDS)
#define MH_OFF_BYTES (MH_OFF_WORDS * 4)
#define GEMM_SMEM ((4 * STG_WORDS + 128 * MH_STRIDE) * 4)   // 190464

__global__ __launch_bounds__(512, 1) void conv_gemm_fused(const int* __restrict__ off,
                                                          const int* __restrict__ col,
                                                          const __half* __restrict__ xsrc16,
                                                          const __half* __restrict__ x16,
                                                          const __half* __restrict__ Wt16,
                                                          const float* __restrict__ bias,
                                                          float* __restrict__ out32,
                                                          __half* __restrict__ out16, int M) {
    extern __shared__ unsigned sm[];
    int tid = threadIdx.x;
    int warp = tid >> 5, lane = tid & 31;
    int g = lane >> 2, t = lane & 3;
    int wr = warp >> 2, wc = warp & 3;       // 4x4 warp grid
    int m_w = wr * 32, n_w = wc * 64;        // warp tile 32x64
    int bm = blockIdx.x * BM;

    int prow = tid >> 2;                     // 0..127
    int pc = tid & 3;

    float c[2][8][4];
#pragma unroll
    for (int i = 0; i < 2; i++)
#pragma unroll
        for (int j = 0; j < 8; j++)
#pragma unroll
            for (int q = 0; q < 4; q++) c[i][j][q] = 0.f;

    auto prefetch = [&](int tile, int slot) {
        int k0 = tile * BK;
        unsigned* Ad = sm + slot * STG_WORDS;
        unsigned* Bd = Ad + A_WORDS;
        if (k0 < 256) {   // A staged only for x16 half
            bool v = (bm + prow) < M;
            const __half* gp = x16 + (size_t)(v ? bm + prow : 0) * H + k0 + pc * 8;
            cp16(Ad + prow * RSTR + pc * 4, gp, v);
        }
#pragma unroll
        for (int r = 0; r < 2; r++) {
            int row = prow + r * 128;
            cp16(Bd + row * RSTR + pc * 4,
                 Wt16 + (size_t)row * 512 + k0 + pc * 8, true);
        }
        cp_commit();
    };

    prefetch(0, 0);
    prefetch(1, 1);
    prefetch(2, 2);

    unsigned sb = (unsigned)__cvta_generic_to_shared(sm);
    unsigned aOff = (unsigned)((m_w + (lane & 15)) * RSTR) * 4 + (unsigned)(lane >> 4) * 16;
    unsigned aOffMh = MH_OFF_BYTES + (unsigned)((m_w + (lane & 15)) * MH_STRIDE) * 4 +
                      (unsigned)(lane >> 4) * 16;
    unsigned bOff = (unsigned)A_WORDS * 4 +
                    (unsigned)((n_w + (lane & 7) + ((lane >> 4) << 3)) * RSTR) * 4 +
                    (unsigned)((lane >> 3) & 1) * 16;

    const __half2 inf2 = __halves2half2(__ushort_as_half(0x7C00), __ushort_as_half(0x7C00));

    for (int it = 0; it < 16; it++) {
        if (it <= 13) cp_wait<2>();
        else if (it == 14) cp_wait<1>();
        else cp_wait<0>();
        __syncthreads();

        int slot = it & 3;
        unsigned aBase = (it < 8) ? (sb + slot * STG_BYTES + aOff)
                                  : (sb + aOffMh + (unsigned)(it - 8) * 64);
        unsigned bBase = sb + slot * STG_BYTES + bOff;
#pragma unroll
        for (int ks = 0; ks < 2; ks++) {
            unsigned kB = ks * 32;
            unsigned a[2][4], b[8][2];
#pragma unroll
            for (int i = 0; i < 2; i++)
                ldsm_x4(a[i][0], a[i][1], a[i][2], a[i][3],
                        aBase + i * 16 * ((it < 8) ? RSTR : MH_STRIDE) * 4 + kB);
#pragma unroll
            for (int jj = 0; jj < 4; jj++)
                ldsm_x4(b[2 * jj][0], b[2 * jj][1], b[2 * jj + 1][0], b[2 * jj + 1][1],
                        bBase + jj * (16 * RSTR * 4) + kB);
#pragma unroll
            for (int i = 0; i < 2; i++)
#pragma unroll
                for (int j = 0; j < 8; j++) mma_fp16(c[i][j], a[i], b[j]);
        }

        if (it + 3 <= 15) prefetch(it + 3, (it + 3) & 3);

        // interleaved segment-min: warp w computes row w*8+it during first 8 iters
        if (it < 8) {
            int rl = (warp << 3) + it;
            int r = bm + rl;
            if (r < M) {
                int beg = off[r], end = off[r + 1];
                __half2 m[4];
#pragma unroll
                for (int q = 0; q < 4; q++) m[q] = inf2;
                for (int j = beg; j < end; j += 4) {
                    int c0 = col[j];
                    int c1 = (j + 1 < end) ? col[j + 1] : c0;
                    int c2 = (j + 2 < end) ? col[j + 2] : c0;
                    int c3 = (j + 3 < end) ? col[j + 3] : c0;
                    uint4 v0 = reinterpret_cast<const uint4*>(xsrc16 + (size_t)c0 * H)[lane];
                    uint4 v1 = reinterpret_cast<const uint4*>(xsrc16 + (size_t)c1 * H)[lane];
                    uint4 v2 = reinterpret_cast<const uint4*>(xsrc16 + (size_t)c2 * H)[lane];
                    uint4 v3 = reinterpret_cast<const uint4*>(xsrc16 + (size_t)c3 * H)[lane];
                    const __half2* h0 = reinterpret_cast<const __half2*>(&v0);
                    const __half2* h1 = reinterpret_cast<const __half2*>(&v1);
                    const __half2* h2 = reinterpret_cast<const __half2*>(&v2);
                    const __half2* h3 = reinterpret_cast<const __half2*>(&v3);
#pragma unroll
                    for (int q = 0; q < 4; q++) {
                        __half2 a2 = __hmin2(h0[q], h1[q]);
                        __half2 b2 = __hmin2(h2[q], h3[q]);
                        m[q] = __hmin2(m[q], __hmin2(a2, b2));
                    }
                }
                uint4 xd = reinterpret_cast<const uint4*>(x16 + (size_t)r * H)[lane];
                const __half2* hx = reinterpret_cast<const __half2*>(&xd);
                uint4 outv;
                __half2* oh = reinterpret_cast<__half2*>(&outv);
                if (beg < end) {
#pragma unroll
                    for (int q = 0; q < 4; q++) oh[q] = __hsub2(hx[q], m[q]);
                } else {
                    outv = make_uint4(0, 0, 0, 0);
                }
                *reinterpret_cast<uint4*>(sm + MH_OFF_WORDS + rl * MH_STRIDE + lane * 4) = outv;
            }
        }
    }

    // epilogue: out = x16 + leaky(c + bias)
#pragma unroll
    for (int i = 0; i < 2; i++) {
        int r0 = bm + m_w + i * 16 + g;
        int r1 = r0 + 8;
#pragma unroll
        for (int j = 0; j < 8; j++) {
            int col2 = n_w + j * 8 + t * 2;
            float b0 = bias[col2], b1 = bias[col2 + 1];
            if (r0 < M) {
                size_t o = (size_t)r0 * H + col2;
                float2 xf = __half22float2(*reinterpret_cast<const __half2*>(x16 + o));
                float v0 = xf.x + leaky(c[i][j][0] + b0);
                float v1 = xf.y + leaky(c[i][j][1] + b1);
                if (out32) { out32[o] = v0; out32[o + 1] = v1; }
                if (out16) *reinterpret_cast<__half2*>(out16 + o) = __floats2half2_rn(v0, v1);
            }
            if (r1 < M) {
                size_t o = (size_t)r1 * H + col2;
                float2 xf = __half22float2(*reinterpret_cast<const __half2*>(x16 + o));
                float v0 = xf.x + leaky(c[i][j][2] + b0);
                float v1 = xf.y + leaky(c[i][j][3] + b1);
                if (out32) { out32[o] = v0; out32[o + 1] = v1; }
                if (out16) *reinterpret_cast<__half2*>(out16 + o) = __floats2half2_rn(v0, v1);
            }
        }
    }
}

// ---------- launch ----------
static inline int cdiv(int a, int b) { return (a + b - 1) / b; }

extern "C" void kernel_launch(void* const* d_in, const int* in_sizes, int n_in,
                              void* d_out, int out_size) {
    const float* vp  = (const float*)d_in[0];
    const float* ec  = (const float*)d_in[1];
    const float* ecp = (const float*)d_in[2];
    const float* ecf = (const float*)d_in[3];
    const float* lt  = (const float*)d_in[4];
    const float* fs  = (const float*)d_in[5];
    const float* fsp = (const float*)d_in[6];
    const float* fsf = (const float*)d_in[7];
    const int* ev = (const int*)d_in[8];
    const int* le = (const int*)d_in[9];
    const int* fl = (const int*)d_in[10];
    const float* Wv = (const float*)d_in[11]; const float* bv = (const float*)d_in[12];
    const float* We = (const float*)d_in[13]; const float* be = (const float*)d_in[14];
    const float* Wl = (const float*)d_in[15]; const float* bl = (const float*)d_in[16];
    const float* Wf = (const float*)d_in[17]; const float* bf = (const float*)d_in[18];
    const float* Wve = (const float*)d_in[19]; const float* bve = (const float*)d_in[20];
    const float* Wel = (const float*)d_in[21]; const float* bel = (const float*)d_in[22];
    const float* Wlf = (const float*)d_in[23]; const float* blf = (const float*)d_in[24];

    int NVn = in_sizes[0] / 3;
    int NEn = in_sizes[1] / 8;
    int NLn = in_sizes[4] / 10;
    int NFn = in_sizes[5] / 12;
    int nEV = in_sizes[8] / 2;
    int nLE = in_sizes[9] / 2;
    int nFL = in_sizes[10] / 2;

    __half *pv16, *pe16, *peo16, *pl16, *pf16, *pwt16;
    int *pcnt, *poff, *pcur, *pcol, *pbsum;
    cudaGetSymbolAddress((void**)&pv16,  g_v16);
    cudaGetSymbolAddress((void**)&pe16,  g_e16);
    cudaGetSymbolAddress((void**)&peo16, g_eo16);
    cudaGetSymbolAddress((void**)&pl16,  g_l16);
    cudaGetSymbolAddress((void**)&pf16,  g_f16);
    cudaGetSymbolAddress((void**)&pwt16, g_wt16);
    cudaGetSymbolAddress((void**)&pcnt,  g_cnt);
    cudaGetSymbolAddress((void**)&poff,  g_off);
    cudaGetSymbolAddress((void**)&pcur,  g_cur);
    cudaGetSymbolAddress((void**)&pcol,  g_col);
    cudaGetSymbolAddress((void**)&pbsum, g_bsum);

    cudaFuncSetAttribute(conv_gemm_fused, cudaFuncAttributeMaxDynamicSharedMemorySize, GEMM_SMEM);

    int nPairTot = nEV + nLE + nFL;
    int nmax = NEn;

    // prep: weight transposes + degree counts (after memset)
    cudaMemsetAsync(pcnt, 0, (size_t)CSRTOT * sizeof(int));
    prep_kernel<<<384 + cdiv(nPairTot, 256), 256>>>(Wve, Wel, Wlf, pwt16,
                                                    ev, nEV, le, nLE, fl, nFL, pcnt);
    {
        dim3 g1(cdiv(nmax, 4096), 3);
        scan_phase1<<<g1, 1024>>>(pcnt, NEn, NLn, NFn, poff, pbsum);
        scan_phase2<<<3, 64>>>(pbsum, NEn, NLn, NFn, poff);
        dim3 g3(cdiv(nmax, 256), 3);
        scan_phase3<<<g3, 256>>>(poff, pbsum, NEn, NLn, NFn, pcur);
    }
    fill_all_kernel<<<cdiv(nPairTot, 256), 256>>>(ev, nEV, le, nLE, fl, nFL, pcur, pcol);

    // embeddings: all four in one launch
    {
        int nbv = cdiv(NVn, 32), nbe = cdiv(NEn, 32), nbl = cdiv(NLn, 32), nbf = cdiv(NFn, 32);
        embed_all<<<nbv + nbe + nbl + nbf, 256>>>(vp, ec, ecp, ecf, lt, fs, fsp, fsf,
                                                  Wv, bv, We, be, Wl, bl, Wf, bf,
                                                  pv16, pe16, pl16, pf16,
                                                  NVn, NEn, NLn, NFn, nbv, nbe, nbl);
    }

    // conv 1: vertices -> edges (segmin fused into GEMM)
    conv_gemm_fused<<<cdiv(NEn, BM), 512, GEMM_SMEM>>>(poff + OFF0, pcol, pv16, pe16,
                                                       pwt16, bve, nullptr, peo16, NEn);
    // conv 2: edges -> loops (fp16 out reuses g_v16)
    conv_gemm_fused<<<cdiv(NLn, BM), 512, GEMM_SMEM>>>(poff + OFF1, pcol + nEV, peo16, pl16,
                                                       pwt16 + 512 * 256, bel, nullptr, pv16, NLn);
    // conv 3: loops -> faces (fp32 output = d_out)
    conv_gemm_fused<<<cdiv(NFn, BM), 512, GEMM_SMEM>>>(poff + OFF2, pcol + nEV + nLE, pv16, pf16,
                                                       pwt16 + 2 * 512 * 256, blf, (float*)d_out, nullptr, NFn);
}

// round 15
// speedup vs baseline: 1.1040x; 1.1040x over previous
#include <cuda_runtime.h>
#include <cuda_fp16.h>
#include <cstdint>

#define H 256

#define MAXV 100000
#define MAXE 150000
#define MAXL 80000
#define MAXF 60000
#define MAXPAIR 800000

#define OFF0 0
#define OFF1 (MAXE + 1)
#define OFF2 (MAXE + 1 + MAXL + 1)
#define CSRTOT (MAXE + MAXL + MAXF + 3)

// scratch (fp16 activations only)
__device__ __half   g_v16[(size_t)MAXV * H];   // vertex embed; reused as conv2-output
__device__ __half   g_e16[(size_t)MAXE * H];
__device__ __half   g_eo16[(size_t)MAXE * H];  // conv1 output
__device__ __half   g_l16[(size_t)MAXL * H];
__device__ __half   g_f16[(size_t)MAXF * H];
__device__ __half   g_mh16[(size_t)MAXE * H];
__device__ __half   g_wt16[3][512 * 256];      // transposed weights [256 n][512 k]
__device__ int      g_cnt[CSRTOT];
__device__ int      g_off[CSRTOT];
__device__ int      g_cur[CSRTOT];
__device__ int      g_col[MAXPAIR];
__device__ int      g_bsum[192];

// ---------- helpers ----------
__device__ __forceinline__ float leaky(float a) { return a >= 0.f ? a : 0.01f * a; }

__device__ __forceinline__ void mma_fp16(float c[4], const unsigned a[4], const unsigned b[2]) {
    asm volatile(
        "mma.sync.aligned.m16n8k16.row.col.f32.f16.f16.f32 "
        "{%0,%1,%2,%3},{%4,%5,%6,%7},{%8,%9},{%0,%1,%2,%3};"
        : "+f"(c[0]), "+f"(c[1]), "+f"(c[2]), "+f"(c[3])
        : "r"(a[0]), "r"(a[1]), "r"(a[2]), "r"(a[3]), "r"(b[0]), "r"(b[1]));
}

__device__ __forceinline__ void ldsm_x4(unsigned& r0, unsigned& r1, unsigned& r2, unsigned& r3,
                                        unsigned addr) {
    asm volatile("ldmatrix.sync.aligned.m8n8.x4.shared.b16 {%0,%1,%2,%3}, [%4];"
                 : "=r"(r0), "=r"(r1), "=r"(r2), "=r"(r3) : "r"(addr));
}

__device__ __forceinline__ void cp16(void* s, const void* g, bool valid) {
    unsigned saddr = (unsigned)__cvta_generic_to_shared(s);
    int sz = valid ? 16 : 0;
    asm volatile("cp.async.cg.shared.global [%0], [%1], 16, %2;" :: "r"(saddr), "l"(g), "r"(sz));
}
__device__ __forceinline__ void cp_commit() { asm volatile("cp.async.commit_group;"); }
template<int N> __device__ __forceinline__ void cp_wait() { asm volatile("cp.async.wait_group %0;" :: "n"(N)); }

// ---------- embedding body: fp16 output only ----------
template<int W0, int W1, int W2>
__device__ __forceinline__ void embed_body(int blk,
                                           const float* __restrict__ s0,
                                           const float* __restrict__ s1,
                                           const float* __restrict__ s2,
                                           const float* __restrict__ W,
                                           const float* __restrict__ bias,
                                           __half* __restrict__ out16, int n) {
    const int RB = 32;
    const int IN = W0 + W1 + W2;
    __shared__ float xs[RB][IN + 1];
    int row0 = blk * RB;
    int tid = threadIdx.x;
    int cg = tid & 63, rg = tid >> 6;

    for (int i = tid; i < RB * IN; i += 256) {
        int r = i / IN, k = i % IN;
        int row = row0 + r;
        float v = 0.f;
        if (row < n) {
            if (k < W0)            v = s0[(size_t)row * W0 + k];
            else if (k < W0 + W1)  v = s1[(size_t)row * W1 + (k - W0)];
            else                   v = s2[row];
        }
        xs[r][k] = v;
    }
    __syncthreads();

    float4 b = reinterpret_cast<const float4*>(bias)[cg];
    float4 acc[8];
#pragma unroll
    for (int q = 0; q < 8; q++) acc[q] = b;
#pragma unroll
    for (int k = 0; k < IN; k++) {
        float4 w = reinterpret_cast<const float4*>(W + (size_t)k * H)[cg];
#pragma unroll
        for (int q = 0; q < 8; q++) {
            float xv = xs[rg * 8 + q][k];
            acc[q].x += xv * w.x; acc[q].y += xv * w.y;
            acc[q].z += xv * w.z; acc[q].w += xv * w.w;
        }
    }
#pragma unroll
    for (int q = 0; q < 8; q++) {
        int row = row0 + rg * 8 + q;
        if (row < n) {
            uint2 o;
            __half2* oh = reinterpret_cast<__half2*>(&o);
            oh[0] = __floats2half2_rn(leaky(acc[q].x), leaky(acc[q].y));
            oh[1] = __floats2half2_rn(leaky(acc[q].z), leaky(acc[q].w));
            reinterpret_cast<uint2*>(out16 + (size_t)row * H)[cg] = o;
        }
    }
}

// all 4 embeddings in one launch
__global__ void embed_all(const float* __restrict__ vp,
                          const float* __restrict__ ec, const float* __restrict__ ecp,
                          const float* __restrict__ ecf,
                          const float* __restrict__ lt,
                          const float* __restrict__ fs, const float* __restrict__ fsp,
                          const float* __restrict__ fsf,
                          const float* __restrict__ Wv, const float* __restrict__ bv,
                          const float* __restrict__ We, const float* __restrict__ be,
                          const float* __restrict__ Wl, const float* __restrict__ bl,
                          const float* __restrict__ Wf, const float* __restrict__ bf,
                          __half* __restrict__ pv16, __half* __restrict__ pe16,
                          __half* __restrict__ pl16, __half* __restrict__ pf16,
                          int NVn, int NEn, int NLn, int NFn,
                          int nbv, int nbe, int nbl) {
    int b = blockIdx.x;
    if (b < nbv)                 embed_body<3, 0, 0>(b, vp, nullptr, nullptr, Wv, bv, pv16, NVn);
    else if (b < nbv + nbe)      embed_body<8, 6, 1>(b - nbv, ec, ecp, ecf, We, be, pe16, NEn);
    else if (b < nbv + nbe + nbl)embed_body<10, 0, 0>(b - nbv - nbe, lt, nullptr, nullptr, Wl, bl, pl16, NLn);
    else                         embed_body<12, 4, 1>(b - nbv - nbe - nbl, fs, fsp, fsf, Wf, bf, pf16, NFn);
}

// ---------- merged prep: weight transposes (blocks 0..383) + degree count (rest) ----------
__global__ void prep_kernel(const float* __restrict__ Wv0, const float* __restrict__ Wv1,
                            const float* __restrict__ Wv2, __half* __restrict__ Wt,
                            const int* __restrict__ d0, int n0,
                            const int* __restrict__ d1, int n1,
                            const int* __restrict__ d2, int n2,
                            int* __restrict__ cnt) {
    int b = blockIdx.x;
    if (b < 384) {
        __shared__ float tt[32][33];
        int z = b / 128, rem = b % 128;
        int bx = (rem & 15) * 32;   // k
        int by = (rem >> 4) * 32;   // n
        const float* W = (z == 0) ? Wv0 : (z == 1) ? Wv1 : Wv2;
        __half* O = Wt + (size_t)z * 512 * 256;
        int tx = threadIdx.x & 31, ty = threadIdx.x >> 5;  // 32 x 8
#pragma unroll
        for (int i = 0; i < 4; i++)
            tt[ty + i * 8][tx] = W[(size_t)(bx + ty + i * 8) * 256 + by + tx];
        __syncthreads();
#pragma unroll
        for (int i = 0; i < 4; i++)
            O[(size_t)(by + ty + i * 8) * 512 + bx + tx] = __float2half_rn(tt[tx][ty + i * 8]);
    } else {
        int i = (b - 384) * 256 + threadIdx.x;
        if (i < n0)                atomicAdd(&cnt[OFF0 + d0[i]], 1);
        else if (i < n0 + n1)      atomicAdd(&cnt[OFF1 + d1[i - n0]], 1);
        else if (i < n0 + n1 + n2) atomicAdd(&cnt[OFF2 + d2[i - n0 - n1]], 1);
    }
}

__global__ void scan_phase1(const int* __restrict__ cnt, int na, int nb_, int nc,
                            int* __restrict__ off, int* __restrict__ bsum) {
    __shared__ int wsum[32];
    int conv = blockIdx.y;
    int n = (conv == 0) ? na : (conv == 1) ? nb_ : nc;
    if (blockIdx.x * 4096 >= n) return;
    int base0 = (conv == 0) ? OFF0 : (conv == 1) ? OFF1 : OFF2;
    const int* c = cnt + base0;
    int* o = off + base0;
    int tid = threadIdx.x, lane = tid & 31, wid = tid >> 5;
    int base = blockIdx.x * 4096 + tid * 4;
    int v0 = (base     < n) ? c[base]     : 0;
    int v1 = (base + 1 < n) ? c[base + 1] : 0;
    int v2 = (base + 2 < n) ? c[base + 2] : 0;
    int v3 = (base + 3 < n) ? c[base + 3] : 0;
    int s = v0 + v1 + v2 + v3;
    int x = s;
#pragma unroll
    for (int d = 1; d < 32; d <<= 1) {
        int y = __shfl_up_sync(~0u, x, d);
        if (lane >= d) x += y;
    }
    if (lane == 31) wsum[wid] = x;
    __syncthreads();
    if (wid == 0) {
        int w = wsum[lane];
#pragma unroll
        for (int d = 1; d < 32; d <<= 1) {
            int y = __shfl_up_sync(~0u, w, d);
            if (lane >= d) w += y;
        }
        wsum[lane] = w;
    }
    __syncthreads();
    int run = x - s + (wid ? wsum[wid - 1] : 0);
    if (base     < n) o[base]     = run; run += v0;
    if (base + 1 < n) o[base + 1] = run; run += v1;
    if (base + 2 < n) o[base + 2] = run; run += v2;
    if (base + 3 < n) o[base + 3] = run;
    if (tid == 0) bsum[conv * 64 + blockIdx.x] = wsum[31];
}

__global__ void scan_phase2(int* __restrict__ bsum, int na, int nb_, int nc,
                            int* __restrict__ off) {
    __shared__ int tmp[64];
    int conv = blockIdx.x;
    int n = (conv == 0) ? na : (conv == 1) ? nb_ : nc;
    int base0 = (conv == 0) ? OFF0 : (conv == 1) ? OFF1 : OFF2;
    int* bs = bsum + conv * 64;
    int nb = (n + 4095) / 4096;
    int tid = threadIdx.x;
    int v = (tid < nb) ? bs[tid] : 0;
    tmp[tid] = v;
    __syncthreads();
    int x = v;
    for (int d = 1; d < 64; d <<= 1) {
        int y = (tid >= d) ? tmp[tid - d] : 0;
        __syncthreads();
        x += y;
        tmp[tid] = x;
        __syncthreads();
    }
    if (tid < nb) bs[tid] = x - v;
    if (tid == 63) off[base0 + n] = x;
}

__global__ void scan_phase3(int* __restrict__ off, const int* __restrict__ bsum,
                            int na, int nb_, int nc, int* __restrict__ cur) {
    int conv = blockIdx.y;
    int n = (conv == 0) ? na : (conv == 1) ? nb_ : nc;
    int i = blockIdx.x * blockDim.x + threadIdx.x;
    if (i >= n) return;
    int base0 = (conv == 0) ? OFF0 : (conv == 1) ? OFF1 : OFF2;
    int o = off[base0 + i] + bsum[conv * 64 + (i >> 12)];
    off[base0 + i] = o;
    cur[base0 + i] = o;
}

__global__ void fill_all_kernel(const int* __restrict__ e0, int n0,
                                const int* __restrict__ e1, int n1,
                                const int* __restrict__ e2, int n2,
                                int* __restrict__ cur, int* __restrict__ col) {
    int i = blockIdx.x * blockDim.x + threadIdx.x;
    const int* idx; int j, np, base0, cbase;
    if (i < n0)                { idx = e0; j = i;           np = n0; base0 = OFF0; cbase = 0; }
    else if (i < n0 + n1)      { idx = e1; j = i - n0;      np = n1; base0 = OFF1; cbase = n0; }
    else if (i < n0 + n1 + n2) { idx = e2; j = i - n0 - n1; np = n2; base0 = OFF2; cbase = n0 + n1; }
    else return;
    int d = idx[j];
    int s = idx[j + np];
    int pos = atomicAdd(&cur[base0 + d], 1);
    col[cbase + pos] = s;
}

// ---------- fused segment-min (fp16, MLP=4) + (x_dst - min) -> fp16 ----------
__global__ void segmin_csr_kernel(const int* __restrict__ off, const int* __restrict__ col,
                                  int n_dst,
                                  const __half* __restrict__ xsrc16,
                                  const __half* __restrict__ xdst16,
                                  __half* __restrict__ mh16) {
    int w = (blockIdx.x * blockDim.x + threadIdx.x) >> 5;
    int lane = threadIdx.x & 31;
    if (w >= n_dst) return;
    int beg = off[w], end = off[w + 1];
    __half2 m[4];
    const __half2 inf2 = __halves2half2(__ushort_as_half(0x7C00), __ushort_as_half(0x7C00));
#pragma unroll
    for (int q = 0; q < 4; q++) m[q] = inf2;

    for (int j = beg; j < end; j += 4) {
        int c0 = col[j];
        int c1 = (j + 1 < end) ? col[j + 1] : c0;
        int c2 = (j + 2 < end) ? col[j + 2] : c0;
        int c3 = (j + 3 < end) ? col[j + 3] : c0;
        uint4 v0 = reinterpret_cast<const uint4*>(xsrc16 + (size_t)c0 * H)[lane];
        uint4 v1 = reinterpret_cast<const uint4*>(xsrc16 + (size_t)c1 * H)[lane];
        uint4 v2 = reinterpret_cast<const uint4*>(xsrc16 + (size_t)c2 * H)[lane];
        uint4 v3 = reinterpret_cast<const uint4*>(xsrc16 + (size_t)c3 * H)[lane];
        const __half2* h0 = reinterpret_cast<const __half2*>(&v0);
        const __half2* h1 = reinterpret_cast<const __half2*>(&v1);
        const __half2* h2 = reinterpret_cast<const __half2*>(&v2);
        const __half2* h3 = reinterpret_cast<const __half2*>(&v3);
#pragma unroll
        for (int q = 0; q < 4; q++) {
            __half2 a = __hmin2(h0[q], h1[q]);
            __half2 b = __hmin2(h2[q], h3[q]);
            m[q] = __hmin2(m[q], __hmin2(a, b));
        }
    }

    uint4 xd = reinterpret_cast<const uint4*>(xdst16 + (size_t)w * H)[lane];
    const __half2* hx = reinterpret_cast<const __half2*>(&xd);
    uint4 outv;
    __half2* oh = reinterpret_cast<__half2*>(&outv);
    if (beg < end) {
#pragma unroll
        for (int q = 0; q < 4; q++) oh[q] = __hsub2(hx[q], m[q]);
    } else {
        outv = make_uint4(0, 0, 0, 0);
    }
    reinterpret_cast<uint4*>(mh16 + (size_t)w * H)[lane] = outv;
}

// ---------- fp16 tensor-core conv GEMM: 128x256 tile, 16 warps, ldmatrix, 4-stage ----------
#define BM 128
#define BK 32
#define RSTR 20                     // row stride in 32-bit words (16 used + 4 pad)
#define A_WORDS (128 * RSTR)        // 2560
#define B_WORDS (256 * RSTR)        // 5120
#define STG_WORDS (A_WORDS + B_WORDS)
#define STG_BYTES (STG_WORDS * 4)   // 30720
#define GEMM_SMEM (4 * STG_BYTES)   // 122880

__global__ __launch_bounds__(512, 1) void conv_gemm_fp16(const __half* __restrict__ x16,
                                                         const __half* __restrict__ mh16,
                                                         const __half* __restrict__ Wt16,
                                                         const float* __restrict__ bias,
                                                         float* __restrict__ out32,
                                                         __half* __restrict__ out16, int M) {
    extern __shared__ unsigned sm[];
    int tid = threadIdx.x;
    int warp = tid >> 5, lane = tid & 31;
    int g = lane >> 2, t = lane & 3;
    int wr = warp >> 2, wc = warp & 3;       // 4x4 warp grid
    int m_w = wr * 32, n_w = wc * 64;        // warp tile 32x64
    int bm = blockIdx.x * BM;

    int prow = tid >> 2;                     // 0..127
    int pc = tid & 3;

    float c[2][8][4];
#pragma unroll
    for (int i = 0; i < 2; i++)
#pragma unroll
        for (int j = 0; j < 8; j++)
#pragma unroll
            for (int q = 0; q < 4; q++) c[i][j][q] = 0.f;

    auto prefetch = [&](int tile, int slot) {
        int k0 = tile * BK;
        const __half* Ab = (k0 < 256) ? x16 : mh16;
        int kk = k0 & 255;
        unsigned* Ad = sm + slot * STG_WORDS;
        unsigned* Bd = Ad + A_WORDS;
        {
            bool v = (bm + prow) < M;
            const __half* gp = Ab + (size_t)(v ? bm + prow : 0) * H + kk + pc * 8;
            cp16(Ad + prow * RSTR + pc * 4, gp, v);
        }
#pragma unroll
        for (int r = 0; r < 2; r++) {
            int row = prow + r * 128;
            cp16(Bd + row * RSTR + pc * 4,
                 Wt16 + (size_t)row * 512 + k0 + pc * 8, true);
        }
        cp_commit();
    };

    prefetch(0, 0);
    prefetch(1, 1);
    prefetch(2, 2);

    unsigned sb = (unsigned)__cvta_generic_to_shared(sm);
    unsigned aOff = (unsigned)((m_w + (lane & 15)) * RSTR) * 4 + (unsigned)(lane >> 4) * 16;
    unsigned bOff = (unsigned)A_WORDS * 4 +
                    (unsigned)((n_w + (lane & 7) + ((lane >> 4) << 3)) * RSTR) * 4 +
                    (unsigned)((lane >> 3) & 1) * 16;

    for (int it = 0; it < 16; it++) {
        if (it <= 13) cp_wait<2>();
        else if (it == 14) cp_wait<1>();
        else cp_wait<0>();
        __syncthreads();

        // early prefetch: slot (it+3)&3 == (it-1)&3 was consumed at it-1 -> safe after barrier
        if (it + 3 <= 15) prefetch(it + 3, (it + 3) & 3);

        int slot = it & 3;
        unsigned aBase = sb + slot * STG_BYTES + aOff;
        unsigned bBase = sb + slot * STG_BYTES + bOff;
#pragma unroll
        for (int ks = 0; ks < 2; ks++) {
            unsigned kB = ks * 32;
            unsigned a[2][4], b[8][2];
#pragma unroll
            for (int i = 0; i < 2; i++)
                ldsm_x4(a[i][0], a[i][1], a[i][2], a[i][3], aBase + i * (16 * RSTR * 4) + kB);
#pragma unroll
            for (int jj = 0; jj < 4; jj++)
                ldsm_x4(b[2 * jj][0], b[2 * jj][1], b[2 * jj + 1][0], b[2 * jj + 1][1],
                        bBase + jj * (16 * RSTR * 4) + kB);
#pragma unroll
            for (int i = 0; i < 2; i++)
#pragma unroll
                for (int j = 0; j < 8; j++) mma_fp16(c[i][j], a[i], b[j]);
        }
    }

    // epilogue: out = x16 + leaky(c + bias)
#pragma unroll
    for (int i = 0; i < 2; i++) {
        int r0 = bm + m_w + i * 16 + g;
        int r1 = r0 + 8;
#pragma unroll
        for (int j = 0; j < 8; j++) {
            int col = n_w + j * 8 + t * 2;
            float b0 = bias[col], b1 = bias[col + 1];
            if (r0 < M) {
                size_t o = (size_t)r0 * H + col;
                float2 xf = __half22float2(*reinterpret_cast<const __half2*>(x16 + o));
                float v0 = xf.x + leaky(c[i][j][0] + b0);
                float v1 = xf.y + leaky(c[i][j][1] + b1);
                if (out32) { out32[o] = v0; out32[o + 1] = v1; }
                if (out16) *reinterpret_cast<__half2*>(out16 + o) = __floats2half2_rn(v0, v1);
            }
            if (r1 < M) {
                size_t o = (size_t)r1 * H + col;
                float2 xf = __half22float2(*reinterpret_cast<const __half2*>(x16 + o));
                float v0 = xf.x + leaky(c[i][j][2] + b0);
                float v1 = xf.y + leaky(c[i][j][3] + b1);
                if (out32) { out32[o] = v0; out32[o + 1] = v1; }
                if (out16) *reinterpret_cast<__half2*>(out16 + o) = __floats2half2_rn(v0, v1);
            }
        }
    }
}

// ---------- launch ----------
static inline int cdiv(int a, int b) { return (a + b - 1) / b; }

extern "C" void kernel_launch(void* const* d_in, const int* in_sizes, int n_in,
                              void* d_out, int out_size) {
    const float* vp  = (const float*)d_in[0];
    const float* ec  = (const float*)d_in[1];
    const float* ecp = (const float*)d_in[2];
    const float* ecf = (const float*)d_in[3];
    const float* lt  = (const float*)d_in[4];
    const float* fs  = (const float*)d_in[5];
    const float* fsp = (const float*)d_in[6];
    const float* fsf = (const float*)d_in[7];
    const int* ev = (const int*)d_in[8];
    const int* le = (const int*)d_in[9];
    const int* fl = (const int*)d_in[10];
    const float* Wv = (const float*)d_in[11]; const float* bv = (const float*)d_in[12];
    const float* We = (const float*)d_in[13]; const float* be = (const float*)d_in[14];
    const float* Wl = (const float*)d_in[15]; const float* bl = (const float*)d_in[16];
    const float* Wf = (const float*)d_in[17]; const float* bf = (const float*)d_in[18];
    const float* Wve = (const float*)d_in[19]; const float* bve = (const float*)d_in[20];
    const float* Wel = (const float*)d_in[21]; const float* bel = (const float*)d_in[22];
    const float* Wlf = (const float*)d_in[23]; const float* blf = (const float*)d_in[24];

    int NVn = in_sizes[0] / 3;
    int NEn = in_sizes[1] / 8;
    int NLn = in_sizes[4] / 10;
    int NFn = in_sizes[5] / 12;
    int nEV = in_sizes[8] / 2;
    int nLE = in_sizes[9] / 2;
    int nFL = in_sizes[10] / 2;

    __half *pv16, *pe16, *peo16, *pl16, *pf16, *pmh16, *pwt16;
    int *pcnt, *poff, *pcur, *pcol, *pbsum;
    cudaGetSymbolAddress((void**)&pv16,  g_v16);
    cudaGetSymbolAddress((void**)&pe16,  g_e16);
    cudaGetSymbolAddress((void**)&peo16, g_eo16);
    cudaGetSymbolAddress((void**)&pl16,  g_l16);
    cudaGetSymbolAddress((void**)&pf16,  g_f16);
    cudaGetSymbolAddress((void**)&pmh16, g_mh16);
    cudaGetSymbolAddress((void**)&pwt16, g_wt16);
    cudaGetSymbolAddress((void**)&pcnt,  g_cnt);
    cudaGetSymbolAddress((void**)&poff,  g_off);
    cudaGetSymbolAddress((void**)&pcur,  g_cur);
    cudaGetSymbolAddress((void**)&pcol,  g_col);
    cudaGetSymbolAddress((void**)&pbsum, g_bsum);

    cudaFuncSetAttribute(conv_gemm_fp16, cudaFuncAttributeMaxDynamicSharedMemorySize, GEMM_SMEM);

    int nPairTot = nEV + nLE + nFL;
    int nmax = NEn;

    // merged prep: weight transposes + degree counts (after memset)
    cudaMemsetAsync(pcnt, 0, (size_t)CSRTOT * sizeof(int));
    prep_kernel<<<384 + cdiv(nPairTot, 256), 256>>>(Wve, Wel, Wlf, pwt16,
                                                    ev, nEV, le, nLE, fl, nFL, pcnt);
    {
        dim3 g1(cdiv(nmax, 4096), 3);
        scan_phase1<<<g1, 1024>>>(pcnt, NEn, NLn, NFn, poff, pbsum);
        scan_phase2<<<3, 64>>>(pbsum, NEn, NLn, NFn, poff);
        dim3 g3(cdiv(nmax, 256), 3);
        scan_phase3<<<g3, 256>>>(poff, pbsum, NEn, NLn, NFn, pcur);
    }
    fill_all_kernel<<<cdiv(nPairTot, 256), 256>>>(ev, nEV, le, nLE, fl, nFL, pcur, pcol);

    // embeddings: all four in one launch, fp16 outputs only
    {
        int nbv = cdiv(NVn, 32), nbe = cdiv(NEn, 32), nbl = cdiv(NLn, 32), nbf = cdiv(NFn, 32);
        embed_all<<<nbv + nbe + nbl + nbf, 256>>>(vp, ec, ecp, ecf, lt, fs, fsp, fsf,
                                                  Wv, bv, We, be, Wl, bl, Wf, bf,
                                                  pv16, pe16, pl16, pf16,
                                                  NVn, NEn, NLn, NFn, nbv, nbe, nbl);
    }

    // conv 1: vertices -> edges
    segmin_csr_kernel<<<cdiv(NEn * 32, 256), 256>>>(poff + OFF0, pcol, NEn, pv16, pe16, pmh16);
    conv_gemm_fp16<<<cdiv(NEn, BM), 512, GEMM_SMEM>>>(pe16, pmh16, pwt16, bve, nullptr, peo16, NEn);

    // conv 2: edges -> loops (fp16 out reuses g_v16)
    segmin_csr_kernel<<<cdiv(NLn * 32, 256), 256>>>(poff + OFF1, pcol + nEV, NLn, peo16, pl16, pmh16);
    conv_gemm_fp16<<<cdiv(NLn, BM), 512, GEMM_SMEM>>>(pl16, pmh16, pwt16 + 512 * 256, bel, nullptr, pv16, NLn);

    // conv 3: loops -> faces (fp32 output = d_out)
    segmin_csr_kernel<<<cdiv(NFn * 32, 256), 256>>>(poff + OFF2, pcol + nEV + nLE, NFn, pv16, pf16, pmh16);
    conv_gemm_fp16<<<cdiv(NFn, BM), 512, GEMM_SMEM>>>(pf16, pmh16, pwt16 + 2 * 512 * 256, blf, (float*)d_out, nullptr, NFn);
}

// round 16
// speedup vs baseline: 1.1649x; 1.0552x over previous
#include <cuda_runtime.h>
#include <cuda_fp16.h>
#include <cstdint>

#define H 256

#define MAXV 100000
#define MAXE 150000
#define MAXL 80000
#define MAXF 60000
#define MAXPAIR 800000

#define OFF0 0
#define OFF1 (MAXE + 1)
#define OFF2 (MAXE + 1 + MAXL + 1)
#define CSRTOT (MAXE + MAXL + MAXF + 3)

// scratch (fp16 activations only)
__device__ __half   g_v16[(size_t)MAXV * H];   // vertex embed; reused as conv2-output
__device__ __half   g_e16[(size_t)MAXE * H];
__device__ __half   g_eo16[(size_t)MAXE * H];  // conv1 output
__device__ __half   g_l16[(size_t)MAXL * H];
__device__ __half   g_f16[(size_t)MAXF * H];
__device__ __half   g_mh16[(size_t)MAXE * H];
__device__ __half   g_wt16[3][512 * 256];      // transposed weights [256 n][512 k]
__device__ int      g_cnt[CSRTOT];
__device__ int      g_off[CSRTOT];
__device__ int      g_cur[CSRTOT];
__device__ int      g_col[MAXPAIR];
__device__ int      g_bsum[192];

// ---------- helpers ----------
__device__ __forceinline__ float leaky(float a) { return a >= 0.f ? a : 0.01f * a; }

__device__ __forceinline__ void mma_fp16(float c[4], const unsigned a[4], const unsigned b[2]) {
    asm volatile(
        "mma.sync.aligned.m16n8k16.row.col.f32.f16.f16.f32 "
        "{%0,%1,%2,%3},{%4,%5,%6,%7},{%8,%9},{%0,%1,%2,%3};"
        : "+f"(c[0]), "+f"(c[1]), "+f"(c[2]), "+f"(c[3])
        : "r"(a[0]), "r"(a[1]), "r"(a[2]), "r"(a[3]), "r"(b[0]), "r"(b[1]));
}

__device__ __forceinline__ void ldsm_x4(unsigned& r0, unsigned& r1, unsigned& r2, unsigned& r3,
                                        unsigned addr) {
    asm volatile("ldmatrix.sync.aligned.m8n8.x4.shared.b16 {%0,%1,%2,%3}, [%4];"
                 : "=r"(r0), "=r"(r1), "=r"(r2), "=r"(r3) : "r"(addr));
}

__device__ __forceinline__ void cp16(void* s, const void* g, bool valid) {
    unsigned saddr = (unsigned)__cvta_generic_to_shared(s);
    int sz = valid ? 16 : 0;
    asm volatile("cp.async.cg.shared.global [%0], [%1], 16, %2;" :: "r"(saddr), "l"(g), "r"(sz));
}
__device__ __forceinline__ void cp_commit() { asm volatile("cp.async.commit_group;"); }
template<int N> __device__ __forceinline__ void cp_wait() { asm volatile("cp.async.wait_group %0;" :: "n"(N)); }

// ---------- embedding body: fp16 output only ----------
template<int W0, int W1, int W2>
__device__ __forceinline__ void embed_body(int blk,
                                           const float* __restrict__ s0,
                                           const float* __restrict__ s1,
                                           const float* __restrict__ s2,
                                           const float* __restrict__ W,
                                           const float* __restrict__ bias,
                                           __half* __restrict__ out16, int n) {
    const int RB = 32;
    const int IN = W0 + W1 + W2;
    __shared__ float xs[RB][IN + 1];
    int row0 = blk * RB;
    int tid = threadIdx.x;
    int cg = tid & 63, rg = tid >> 6;

    for (int i = tid; i < RB * IN; i += 256) {
        int r = i / IN, k = i % IN;
        int row = row0 + r;
        float v = 0.f;
        if (row < n) {
            if (k < W0)            v = s0[(size_t)row * W0 + k];
            else if (k < W0 + W1)  v = s1[(size_t)row * W1 + (k - W0)];
            else                   v = s2[row];
        }
        xs[r][k] = v;
    }
    __syncthreads();

    float4 b = reinterpret_cast<const float4*>(bias)[cg];
    float4 acc[8];
#pragma unroll
    for (int q = 0; q < 8; q++) acc[q] = b;
#pragma unroll
    for (int k = 0; k < IN; k++) {
        float4 w = reinterpret_cast<const float4*>(W + (size_t)k * H)[cg];
#pragma unroll
        for (int q = 0; q < 8; q++) {
            float xv = xs[rg * 8 + q][k];
            acc[q].x += xv * w.x; acc[q].y += xv * w.y;
            acc[q].z += xv * w.z; acc[q].w += xv * w.w;
        }
    }
#pragma unroll
    for (int q = 0; q < 8; q++) {
        int row = row0 + rg * 8 + q;
        if (row < n) {
            uint2 o;
            __half2* oh = reinterpret_cast<__half2*>(&o);
            oh[0] = __floats2half2_rn(leaky(acc[q].x), leaky(acc[q].y));
            oh[1] = __floats2half2_rn(leaky(acc[q].z), leaky(acc[q].w));
            reinterpret_cast<uint2*>(out16 + (size_t)row * H)[cg] = o;
        }
    }
}

// all 4 embeddings in one launch
__global__ void embed_all(const float* __restrict__ vp,
                          const float* __restrict__ ec, const float* __restrict__ ecp,
                          const float* __restrict__ ecf,
                          const float* __restrict__ lt,
                          const float* __restrict__ fs, const float* __restrict__ fsp,
                          const float* __restrict__ fsf,
                          const float* __restrict__ Wv, const float* __restrict__ bv,
                          const float* __restrict__ We, const float* __restrict__ be,
                          const float* __restrict__ Wl, const float* __restrict__ bl,
                          const float* __restrict__ Wf, const float* __restrict__ bf,
                          __half* __restrict__ pv16, __half* __restrict__ pe16,
                          __half* __restrict__ pl16, __half* __restrict__ pf16,
                          int NVn, int NEn, int NLn, int NFn,
                          int nbv, int nbe, int nbl) {
    int b = blockIdx.x;
    if (b < nbv)                 embed_body<3, 0, 0>(b, vp, nullptr, nullptr, Wv, bv, pv16, NVn);
    else if (b < nbv + nbe)      embed_body<8, 6, 1>(b - nbv, ec, ecp, ecf, We, be, pe16, NEn);
    else if (b < nbv + nbe + nbl)embed_body<10, 0, 0>(b - nbv - nbe, lt, nullptr, nullptr, Wl, bl, pl16, NLn);
    else                         embed_body<12, 4, 1>(b - nbv - nbe - nbl, fs, fsp, fsf, Wf, bf, pf16, NFn);
}

// ---------- merged prep: weight transposes (blocks 0..383) + degree count (rest) ----------
__global__ void prep_kernel(const float* __restrict__ Wv0, const float* __restrict__ Wv1,
                            const float* __restrict__ Wv2, __half* __restrict__ Wt,
                            const int* __restrict__ d0, int n0,
                            const int* __restrict__ d1, int n1,
                            const int* __restrict__ d2, int n2,
                            int* __restrict__ cnt) {
    int b = blockIdx.x;
    if (b < 384) {
        __shared__ float tt[32][33];
        int z = b / 128, rem = b % 128;
        int bx = (rem & 15) * 32;   // k
        int by = (rem >> 4) * 32;   // n
        const float* W = (z == 0) ? Wv0 : (z == 1) ? Wv1 : Wv2;
        __half* O = Wt + (size_t)z * 512 * 256;
        int tx = threadIdx.x & 31, ty = threadIdx.x >> 5;  // 32 x 8
#pragma unroll
        for (int i = 0; i < 4; i++)
            tt[ty + i * 8][tx] = W[(size_t)(bx + ty + i * 8) * 256 + by + tx];
        __syncthreads();
#pragma unroll
        for (int i = 0; i < 4; i++)
            O[(size_t)(by + ty + i * 8) * 512 + bx + tx] = __float2half_rn(tt[tx][ty + i * 8]);
    } else {
        int i = (b - 384) * 256 + threadIdx.x;
        if (i < n0)                atomicAdd(&cnt[OFF0 + d0[i]], 1);
        else if (i < n0 + n1)      atomicAdd(&cnt[OFF1 + d1[i - n0]], 1);
        else if (i < n0 + n1 + n2) atomicAdd(&cnt[OFF2 + d2[i - n0 - n1]], 1);
    }
}

__global__ void scan_phase1(const int* __restrict__ cnt, int na, int nb_, int nc,
                            int* __restrict__ off, int* __restrict__ bsum) {
    __shared__ int wsum[32];
    int conv = blockIdx.y;
    int n = (conv == 0) ? na : (conv == 1) ? nb_ : nc;
    if (blockIdx.x * 4096 >= n) return;
    int base0 = (conv == 0) ? OFF0 : (conv == 1) ? OFF1 : OFF2;
    const int* c = cnt + base0;
    int* o = off + base0;
    int tid = threadIdx.x, lane = tid & 31, wid = tid >> 5;
    int base = blockIdx.x * 4096 + tid * 4;
    int v0 = (base     < n) ? c[base]     : 0;
    int v1 = (base + 1 < n) ? c[base + 1] : 0;
    int v2 = (base + 2 < n) ? c[base + 2] : 0;
    int v3 = (base + 3 < n) ? c[base + 3] : 0;
    int s = v0 + v1 + v2 + v3;
    int x = s;
#pragma unroll
    for (int d = 1; d < 32; d <<= 1) {
        int y = __shfl_up_sync(~0u, x, d);
        if (lane >= d) x += y;
    }
    if (lane == 31) wsum[wid] = x;
    __syncthreads();
    if (wid == 0) {
        int w = wsum[lane];
#pragma unroll
        for (int d = 1; d < 32; d <<= 1) {
            int y = __shfl_up_sync(~0u, w, d);
            if (lane >= d) w += y;
        }
        wsum[lane] = w;
    }
    __syncthreads();
    int run = x - s + (wid ? wsum[wid - 1] : 0);
    if (base     < n) o[base]     = run; run += v0;
    if (base + 1 < n) o[base + 1] = run; run += v1;
    if (base + 2 < n) o[base + 2] = run; run += v2;
    if (base + 3 < n) o[base + 3] = run;
    if (tid == 0) bsum[conv * 64 + blockIdx.x] = wsum[31];
}

__global__ void scan_phase2(int* __restrict__ bsum, int na, int nb_, int nc,
                            int* __restrict__ off) {
    __shared__ int tmp[64];
    int conv = blockIdx.x;
    int n = (conv == 0) ? na : (conv == 1) ? nb_ : nc;
    int base0 = (conv == 0) ? OFF0 : (conv == 1) ? OFF1 : OFF2;
    int* bs = bsum + conv * 64;
    int nb = (n + 4095) / 4096;
    int tid = threadIdx.x;
    int v = (tid < nb) ? bs[tid] : 0;
    tmp[tid] = v;
    __syncthreads();
    int x = v;
    for (int d = 1; d < 64; d <<= 1) {
        int y = (tid >= d) ? tmp[tid - d] : 0;
        __syncthreads();
        x += y;
        tmp[tid] = x;
        __syncthreads();
    }
    if (tid < nb) bs[tid] = x - v;
    if (tid == 63) off[base0 + n] = x;
}

__global__ void scan_phase3(int* __restrict__ off, const int* __restrict__ bsum,
                            int na, int nb_, int nc, int* __restrict__ cur) {
    int conv = blockIdx.y;
    int n = (conv == 0) ? na : (conv == 1) ? nb_ : nc;
    int i = blockIdx.x * blockDim.x + threadIdx.x;
    if (i >= n) return;
    int base0 = (conv == 0) ? OFF0 : (conv == 1) ? OFF1 : OFF2;
    int o = off[base0 + i] + bsum[conv * 64 + (i >> 12)];
    off[base0 + i] = o;
    cur[base0 + i] = o;
}

__global__ void fill_all_kernel(const int* __restrict__ e0, int n0,
                                const int* __restrict__ e1, int n1,
                                const int* __restrict__ e2, int n2,
                                int* __restrict__ cur, int* __restrict__ col) {
    int i = blockIdx.x * blockDim.x + threadIdx.x;
    const int* idx; int j, np, base0, cbase;
    if (i < n0)                { idx = e0; j = i;           np = n0; base0 = OFF0; cbase = 0; }
    else if (i < n0 + n1)      { idx = e1; j = i - n0;      np = n1; base0 = OFF1; cbase = n0; }
    else if (i < n0 + n1 + n2) { idx = e2; j = i - n0 - n1; np = n2; base0 = OFF2; cbase = n0 + n1; }
    else return;
    int d = idx[j];
    int s = idx[j + np];
    int pos = atomicAdd(&cur[base0 + d], 1);
    col[cbase + pos] = s;
}

// ---------- fused segment-min (fp16, MLP=4) + (x_dst - min) -> fp16 ----------
__global__ void segmin_csr_kernel(const int* __restrict__ off, const int* __restrict__ col,
                                  int n_dst,
                                  const __half* __restrict__ xsrc16,
                                  const __half* __restrict__ xdst16,
                                  __half* __restrict__ mh16) {
    int w = (blockIdx.x * blockDim.x + threadIdx.x) >> 5;
    int lane = threadIdx.x & 31;
    if (w >= n_dst) return;
    int beg = off[w], end = off[w + 1];
    __half2 m[4];
    const __half2 inf2 = __halves2half2(__ushort_as_half(0x7C00), __ushort_as_half(0x7C00));
#pragma unroll
    for (int q = 0; q < 4; q++) m[q] = inf2;

    for (int j = beg; j < end; j += 4) {
        int c0 = col[j];
        int c1 = (j + 1 < end) ? col[j + 1] : c0;
        int c2 = (j + 2 < end) ? col[j + 2] : c0;
        int c3 = (j + 3 < end) ? col[j + 3] : c0;
        uint4 v0 = reinterpret_cast<const uint4*>(xsrc16 + (size_t)c0 * H)[lane];
        uint4 v1 = reinterpret_cast<const uint4*>(xsrc16 + (size_t)c1 * H)[lane];
        uint4 v2 = reinterpret_cast<const uint4*>(xsrc16 + (size_t)c2 * H)[lane];
        uint4 v3 = reinterpret_cast<const uint4*>(xsrc16 + (size_t)c3 * H)[lane];
        const __half2* h0 = reinterpret_cast<const __half2*>(&v0);
        const __half2* h1 = reinterpret_cast<const __half2*>(&v1);
        const __half2* h2 = reinterpret_cast<const __half2*>(&v2);
        const __half2* h3 = reinterpret_cast<const __half2*>(&v3);
#pragma unroll
        for (int q = 0; q < 4; q++) {
            __half2 a = __hmin2(h0[q], h1[q]);
            __half2 b = __hmin2(h2[q], h3[q]);
            m[q] = __hmin2(m[q], __hmin2(a, b));
        }
    }

    uint4 xd = reinterpret_cast<const uint4*>(xdst16 + (size_t)w * H)[lane];
    const __half2* hx = reinterpret_cast<const __half2*>(&xd);
    uint4 outv;
    __half2* oh = reinterpret_cast<__half2*>(&outv);
    if (beg < end) {
#pragma unroll
        for (int q = 0; q < 4; q++) oh[q] = __hsub2(hx[q], m[q]);
    } else {
        outv = make_uint4(0, 0, 0, 0);
    }
    reinterpret_cast<uint4*>(mh16 + (size_t)w * H)[lane] = outv;
}

// ---------- fp16 tensor-core conv GEMM: 128x256 tile, 16 warps, ldmatrix, 4-stage ----------
#define BM 128
#define BK 32
#define RSTR 20                     // row stride in 32-bit words (16 used + 4 pad)
#define A_WORDS (128 * RSTR)        // 2560
#define B_WORDS (256 * RSTR)        // 5120
#define STG_WORDS (A_WORDS + B_WORDS)
#define STG_BYTES (STG_WORDS * 4)   // 30720
#define GEMM_SMEM (4 * STG_BYTES)   // 122880

__global__ __launch_bounds__(512, 1) void conv_gemm_fp16(const __half* __restrict__ x16,
                                                         const __half* __restrict__ mh16,
                                                         const __half* __restrict__ Wt16,
                                                         const float* __restrict__ bias,
                                                         float* __restrict__ out32,
                                                         __half* __restrict__ out16, int M) {
    extern __shared__ unsigned sm[];
    int tid = threadIdx.x;
    int warp = tid >> 5, lane = tid & 31;
    int g = lane >> 2, t = lane & 3;
    int wr = warp >> 2, wc = warp & 3;       // 4x4 warp grid
    int m_w = wr * 32, n_w = wc * 64;        // warp tile 32x64
    int bm = blockIdx.x * BM;

    int prow = tid >> 2;                     // 0..127
    int pc = tid & 3;

    float c[2][8][4];
#pragma unroll
    for (int i = 0; i < 2; i++)
#pragma unroll
        for (int j = 0; j < 8; j++)
#pragma unroll
            for (int q = 0; q < 4; q++) c[i][j][q] = 0.f;

    auto prefetch = [&](int tile, int slot) {
        int k0 = tile * BK;
        const __half* Ab = (k0 < 256) ? x16 : mh16;
        int kk = k0 & 255;
        unsigned* Ad = sm + slot * STG_WORDS;
        unsigned* Bd = Ad + A_WORDS;
        // A: 128 rows x 4 chunks = 512 cp -> 1 per thread
        {
            bool v = (bm + prow) < M;
            const __half* gp = Ab + (size_t)(v ? bm + prow : 0) * H + kk + pc * 8;
            cp16(Ad + prow * RSTR + pc * 4, gp, v);
        }
        // B: 256 rows x 4 chunks = 1024 cp -> 2 per thread
#pragma unroll
        for (int r = 0; r < 2; r++) {
            int row = prow + r * 128;
            cp16(Bd + row * RSTR + pc * 4,
                 Wt16 + (size_t)row * 512 + k0 + pc * 8, true);
        }
        cp_commit();
    };

    prefetch(0, 0);
    prefetch(1, 1);
    prefetch(2, 2);

    unsigned sb = (unsigned)__cvta_generic_to_shared(sm);
    unsigned aOff = (unsigned)((m_w + (lane & 15)) * RSTR) * 4 + (unsigned)(lane >> 4) * 16;
    unsigned bOff = (unsigned)A_WORDS * 4 +
                    (unsigned)((n_w + (lane & 7) + ((lane >> 4) << 3)) * RSTR) * 4 +
                    (unsigned)((lane >> 3) & 1) * 16;

    for (int it = 0; it < 16; it++) {
        if (it <= 13) cp_wait<2>();
        else if (it == 14) cp_wait<1>();
        else cp_wait<0>();
        __syncthreads();

        int slot = it & 3;
        unsigned aBase = sb + slot * STG_BYTES + aOff;
        unsigned bBase = sb + slot * STG_BYTES + bOff;
#pragma unroll
        for (int ks = 0; ks < 2; ks++) {
            unsigned kB = ks * 32;
            unsigned a[2][4], b[8][2];
#pragma unroll
            for (int i = 0; i < 2; i++)
                ldsm_x4(a[i][0], a[i][1], a[i][2], a[i][3], aBase + i * (16 * RSTR * 4) + kB);
#pragma unroll
            for (int jj = 0; jj < 4; jj++)
                ldsm_x4(b[2 * jj][0], b[2 * jj][1], b[2 * jj + 1][0], b[2 * jj + 1][1],
                        bBase + jj * (16 * RSTR * 4) + kB);
#pragma unroll
            for (int i = 0; i < 2; i++)
#pragma unroll
                for (int j = 0; j < 8; j++) mma_fp16(c[i][j], a[i], b[j]);
        }

        if (it + 3 <= 15) prefetch(it + 3, (it + 3) & 3);
    }

    // epilogue: out = x16 + leaky(c + bias)
#pragma unroll
    for (int i = 0; i < 2; i++) {
        int r0 = bm + m_w + i * 16 + g;
        int r1 = r0 + 8;
#pragma unroll
        for (int j = 0; j < 8; j++) {
            int col = n_w + j * 8 + t * 2;
            float b0 = bias[col], b1 = bias[col + 1];
            if (r0 < M) {
                size_t o = (size_t)r0 * H + col;
                float2 xf = __half22float2(*reinterpret_cast<const __half2*>(x16 + o));
                float v0 = xf.x + leaky(c[i][j][0] + b0);
                float v1 = xf.y + leaky(c[i][j][1] + b1);
                if (out32) { out32[o] = v0; out32[o + 1] = v1; }
                if (out16) *reinterpret_cast<__half2*>(out16 + o) = __floats2half2_rn(v0, v1);
            }
            if (r1 < M) {
                size_t o = (size_t)r1 * H + col;
                float2 xf = __half22float2(*reinterpret_cast<const __half2*>(x16 + o));
                float v0 = xf.x + leaky(c[i][j][2] + b0);
                float v1 = xf.y + leaky(c[i][j][3] + b1);
                if (out32) { out32[o] = v0; out32[o + 1] = v1; }
                if (out16) *reinterpret_cast<__half2*>(out16 + o) = __floats2half2_rn(v0, v1);
            }
        }
    }
}

// ---------- launch ----------
static inline int cdiv(int a, int b) { return (a + b - 1) / b; }

extern "C" void kernel_launch(void* const* d_in, const int* in_sizes, int n_in,
                              void* d_out, int out_size) {
    const float* vp  = (const float*)d_in[0];
    const float* ec  = (const float*)d_in[1];
    const float* ecp = (const float*)d_in[2];
    const float* ecf = (const float*)d_in[3];
    const float* lt  = (const float*)d_in[4];
    const float* fs  = (const float*)d_in[5];
    const float* fsp = (const float*)d_in[6];
    const float* fsf = (const float*)d_in[7];
    const int* ev = (const int*)d_in[8];
    const int* le = (const int*)d_in[9];
    const int* fl = (const int*)d_in[10];
    const float* Wv = (const float*)d_in[11]; const float* bv = (const float*)d_in[12];
    const float* We = (const float*)d_in[13]; const float* be = (const float*)d_in[14];
    const float* Wl = (const float*)d_in[15]; const float* bl = (const float*)d_in[16];
    const float* Wf = (const float*)d_in[17]; const float* bf = (const float*)d_in[18];
    const float* Wve = (const float*)d_in[19]; const float* bve = (const float*)d_in[20];
    const float* Wel = (const float*)d_in[21]; const float* bel = (const float*)d_in[22];
    const float* Wlf = (const float*)d_in[23]; const float* blf = (const float*)d_in[24];

    int NVn = in_sizes[0] / 3;
    int NEn = in_sizes[1] / 8;
    int NLn = in_sizes[4] / 10;
    int NFn = in_sizes[5] / 12;
    int nEV = in_sizes[8] / 2;
    int nLE = in_sizes[9] / 2;
    int nFL = in_sizes[10] / 2;

    __half *pv16, *pe16, *peo16, *pl16, *pf16, *pmh16, *pwt16;
    int *pcnt, *poff, *pcur, *pcol, *pbsum;
    cudaGetSymbolAddress((void**)&pv16,  g_v16);
    cudaGetSymbolAddress((void**)&pe16,  g_e16);
    cudaGetSymbolAddress((void**)&peo16, g_eo16);
    cudaGetSymbolAddress((void**)&pl16,  g_l16);
    cudaGetSymbolAddress((void**)&pf16,  g_f16);
    cudaGetSymbolAddress((void**)&pmh16, g_mh16);
    cudaGetSymbolAddress((void**)&pwt16, g_wt16);
    cudaGetSymbolAddress((void**)&pcnt,  g_cnt);
    cudaGetSymbolAddress((void**)&poff,  g_off);
    cudaGetSymbolAddress((void**)&pcur,  g_cur);
    cudaGetSymbolAddress((void**)&pcol,  g_col);
    cudaGetSymbolAddress((void**)&pbsum, g_bsum);

    cudaFuncSetAttribute(conv_gemm_fp16, cudaFuncAttributeMaxDynamicSharedMemorySize, GEMM_SMEM);

    int nPairTot = nEV + nLE + nFL;
    int nmax = NEn;

    // merged prep: weight transposes + degree counts (after memset)
    cudaMemsetAsync(pcnt, 0, (size_t)CSRTOT * sizeof(int));
    prep_kernel<<<384 + cdiv(nPairTot, 256), 256>>>(Wve, Wel, Wlf, pwt16,
                                                    ev, nEV, le, nLE, fl, nFL, pcnt);
    {
        dim3 g1(cdiv(nmax, 4096), 3);
        scan_phase1<<<g1, 1024>>>(pcnt, NEn, NLn, NFn, poff, pbsum);
        scan_phase2<<<3, 64>>>(pbsum, NEn, NLn, NFn, poff);
        dim3 g3(cdiv(nmax, 256), 3);
        scan_phase3<<<g3, 256>>>(poff, pbsum, NEn, NLn, NFn, pcur);
    }
    fill_all_kernel<<<cdiv(nPairTot, 256), 256>>>(ev, nEV, le, nLE, fl, nFL, pcur, pcol);

    // embeddings: all four in one launch, fp16 outputs only
    {
        int nbv = cdiv(NVn, 32), nbe = cdiv(NEn, 32), nbl = cdiv(NLn, 32), nbf = cdiv(NFn, 32);
        embed_all<<<nbv + nbe + nbl + nbf, 256>>>(vp, ec, ecp, ecf, lt, fs, fsp, fsf,
                                                  Wv, bv, We, be, Wl, bl, Wf, bf,
                                                  pv16, pe16, pl16, pf16,
                                                  NVn, NEn, NLn, NFn, nbv, nbe, nbl);
    }

    // conv 1: vertices -> edges
    segmin_csr_kernel<<<cdiv(NEn * 32, 256), 256>>>(poff + OFF0, pcol, NEn, pv16, pe16, pmh16);
    conv_gemm_fp16<<<cdiv(NEn, BM), 512, GEMM_SMEM>>>(pe16, pmh16, pwt16, bve, nullptr, peo16, NEn);

    // conv 2: edges -> loops (fp16 out reuses g_v16)
    segmin_csr_kernel<<<cdiv(NLn * 32, 256), 256>>>(poff + OFF1, pcol + nEV, NLn, peo16, pl16, pmh16);
    conv_gemm_fp16<<<cdiv(NLn, BM), 512, GEMM_SMEM>>>(pl16, pmh16, pwt16 + 512 * 256, bel, nullptr, pv16, NLn);

    // conv 3: loops -> faces (fp32 output = d_out)
    segmin_csr_kernel<<<cdiv(NFn * 32, 256), 256>>>(poff + OFF2, pcol + nEV + nLE, NFn, pv16, pf16, pmh16);
    conv_gemm_fp16<<<cdiv(NFn, BM), 512, GEMM_SMEM>>>(pf16, pmh16, pwt16 + 2 * 512 * 256, blf, (float*)d_out, nullptr, NFn);
}

// round 17
// speedup vs baseline: 1.1981x; 1.0285x over previous
#include <cuda_runtime.h>
#include <cuda_fp16.h>
#include <cstdint>

#define H 256

#define MAXV 100000
#define MAXE 150000
#define MAXL 80000
#define MAXF 60000
#define MAXPAIR 800000

#define OFF0 0
#define OFF1 (MAXE + 1)
#define OFF2 (MAXE + 1 + MAXL + 1)
#define CSRTOT (MAXE + MAXL + MAXF + 3)

// scratch (fp16 activations only)
__device__ __half   g_v16[(size_t)MAXV * H];   // vertex embed; reused as conv2-output
__device__ __half   g_e16[(size_t)MAXE * H];
__device__ __half   g_eo16[(size_t)MAXE * H];  // conv1 output
__device__ __half   g_l16[(size_t)MAXL * H];
__device__ __half   g_f16[(size_t)MAXF * H];
__device__ __half   g_mh16[(size_t)MAXE * H];
__device__ __half   g_wt16[3][512 * 256];      // transposed weights [256 n][512 k]
__device__ int      g_cnt[CSRTOT];
__device__ int      g_off[CSRTOT];
__device__ int      g_cur[CSRTOT];
__device__ int      g_col[MAXPAIR];
__device__ int      g_bsum[192];

// ---------- helpers ----------
__device__ __forceinline__ float leaky(float a) { return a >= 0.f ? a : 0.01f * a; }

__device__ __forceinline__ void mma_fp16(float c[4], const unsigned a[4], const unsigned b[2]) {
    asm volatile(
        "mma.sync.aligned.m16n8k16.row.col.f32.f16.f16.f32 "
        "{%0,%1,%2,%3},{%4,%5,%6,%7},{%8,%9},{%0,%1,%2,%3};"
        : "+f"(c[0]), "+f"(c[1]), "+f"(c[2]), "+f"(c[3])
        : "r"(a[0]), "r"(a[1]), "r"(a[2]), "r"(a[3]), "r"(b[0]), "r"(b[1]));
}

__device__ __forceinline__ void ldsm_x4(unsigned& r0, unsigned& r1, unsigned& r2, unsigned& r3,
                                        unsigned addr) {
    asm volatile("ldmatrix.sync.aligned.m8n8.x4.shared.b16 {%0,%1,%2,%3}, [%4];"
                 : "=r"(r0), "=r"(r1), "=r"(r2), "=r"(r3) : "r"(addr));
}

__device__ __forceinline__ void cp16(void* s, const void* g, bool valid) {
    unsigned saddr = (unsigned)__cvta_generic_to_shared(s);
    int sz = valid ? 16 : 0;
    asm volatile("cp.async.cg.shared.global [%0], [%1], 16, %2;" :: "r"(saddr), "l"(g), "r"(sz));
}
__device__ __forceinline__ void cp_commit() { asm volatile("cp.async.commit_group;"); }
template<int N> __device__ __forceinline__ void cp_wait() { asm volatile("cp.async.wait_group %0;" :: "n"(N)); }

// ---------- embedding body: fp16 output only ----------
template<int W0, int W1, int W2>
__device__ __forceinline__ void embed_body(int blk,
                                           const float* __restrict__ s0,
                                           const float* __restrict__ s1,
                                           const float* __restrict__ s2,
                                           const float* __restrict__ W,
                                           const float* __restrict__ bias,
                                           __half* __restrict__ out16, int n) {
    const int RB = 32;
    const int IN = W0 + W1 + W2;
    __shared__ float xs[RB][IN + 1];
    int row0 = blk * RB;
    int tid = threadIdx.x;
    int cg = tid & 63, rg = tid >> 6;

    for (int i = tid; i < RB * IN; i += 256) {
        int r = i / IN, k = i % IN;
        int row = row0 + r;
        float v = 0.f;
        if (row < n) {
            if (k < W0)            v = s0[(size_t)row * W0 + k];
            else if (k < W0 + W1)  v = s1[(size_t)row * W1 + (k - W0)];
            else                   v = s2[row];
        }
        xs[r][k] = v;
    }
    __syncthreads();

    float4 b = reinterpret_cast<const float4*>(bias)[cg];
    float4 acc[8];
#pragma unroll
    for (int q = 0; q < 8; q++) acc[q] = b;
#pragma unroll
    for (int k = 0; k < IN; k++) {
        float4 w = reinterpret_cast<const float4*>(W + (size_t)k * H)[cg];
#pragma unroll
        for (int q = 0; q < 8; q++) {
            float xv = xs[rg * 8 + q][k];
            acc[q].x += xv * w.x; acc[q].y += xv * w.y;
            acc[q].z += xv * w.z; acc[q].w += xv * w.w;
        }
    }
#pragma unroll
    for (int q = 0; q < 8; q++) {
        int row = row0 + rg * 8 + q;
        if (row < n) {
            uint2 o;
            __half2* oh = reinterpret_cast<__half2*>(&o);
            oh[0] = __floats2half2_rn(leaky(acc[q].x), leaky(acc[q].y));
            oh[1] = __floats2half2_rn(leaky(acc[q].z), leaky(acc[q].w));
            reinterpret_cast<uint2*>(out16 + (size_t)row * H)[cg] = o;
        }
    }
}

// all 4 embeddings in one launch
__global__ void embed_all(const float* __restrict__ vp,
                          const float* __restrict__ ec, const float* __restrict__ ecp,
                          const float* __restrict__ ecf,
                          const float* __restrict__ lt,
                          const float* __restrict__ fs, const float* __restrict__ fsp,
                          const float* __restrict__ fsf,
                          const float* __restrict__ Wv, const float* __restrict__ bv,
                          const float* __restrict__ We, const float* __restrict__ be,
                          const float* __restrict__ Wl, const float* __restrict__ bl,
                          const float* __restrict__ Wf, const float* __restrict__ bf,
                          __half* __restrict__ pv16, __half* __restrict__ pe16,
                          __half* __restrict__ pl16, __half* __restrict__ pf16,
                          int NVn, int NEn, int NLn, int NFn,
                          int nbv, int nbe, int nbl) {
    int b = blockIdx.x;
    if (b < nbv)                 embed_body<3, 0, 0>(b, vp, nullptr, nullptr, Wv, bv, pv16, NVn);
    else if (b < nbv + nbe)      embed_body<8, 6, 1>(b - nbv, ec, ecp, ecf, We, be, pe16, NEn);
    else if (b < nbv + nbe + nbl)embed_body<10, 0, 0>(b - nbv - nbe, lt, nullptr, nullptr, Wl, bl, pl16, NLn);
    else                         embed_body<12, 4, 1>(b - nbv - nbe - nbl, fs, fsp, fsf, Wf, bf, pf16, NFn);
}

// ---------- merged prep: weight transposes (blocks 0..383) + degree count (rest) ----------
__global__ void prep_kernel(const float* __restrict__ Wv0, const float* __restrict__ Wv1,
                            const float* __restrict__ Wv2, __half* __restrict__ Wt,
                            const int* __restrict__ d0, int n0,
                            const int* __restrict__ d1, int n1,
                            const int* __restrict__ d2, int n2,
                            int* __restrict__ cnt) {
    int b = blockIdx.x;
    if (b < 384) {
        __shared__ float tt[32][33];
        int z = b / 128, rem = b % 128;
        int bx = (rem & 15) * 32;   // k
        int by = (rem >> 4) * 32;   // n
        const float* W = (z == 0) ? Wv0 : (z == 1) ? Wv1 : Wv2;
        __half* O = Wt + (size_t)z * 512 * 256;
        int tx = threadIdx.x & 31, ty = threadIdx.x >> 5;  // 32 x 8
#pragma unroll
        for (int i = 0; i < 4; i++)
            tt[ty + i * 8][tx] = W[(size_t)(bx + ty + i * 8) * 256 + by + tx];
        __syncthreads();
#pragma unroll
        for (int i = 0; i < 4; i++)
            O[(size_t)(by + ty + i * 8) * 512 + bx + tx] = __float2half_rn(tt[tx][ty + i * 8]);
    } else {
        int i = (b - 384) * 256 + threadIdx.x;
        if (i < n0)                atomicAdd(&cnt[OFF0 + d0[i]], 1);
        else if (i < n0 + n1)      atomicAdd(&cnt[OFF1 + d1[i - n0]], 1);
        else if (i < n0 + n1 + n2) atomicAdd(&cnt[OFF2 + d2[i - n0 - n1]], 1);
    }
}

__global__ void scan_phase1(const int* __restrict__ cnt, int na, int nb_, int nc,
                            int* __restrict__ off, int* __restrict__ bsum) {
    __shared__ int wsum[32];
    int conv = blockIdx.y;
    int n = (conv == 0) ? na : (conv == 1) ? nb_ : nc;
    if (blockIdx.x * 4096 >= n) return;
    int base0 = (conv == 0) ? OFF0 : (conv == 1) ? OFF1 : OFF2;
    const int* c = cnt + base0;
    int* o = off + base0;
    int tid = threadIdx.x, lane = tid & 31, wid = tid >> 5;
    int base = blockIdx.x * 4096 + tid * 4;
    int v0 = (base     < n) ? c[base]     : 0;
    int v1 = (base + 1 < n) ? c[base + 1] : 0;
    int v2 = (base + 2 < n) ? c[base + 2] : 0;
    int v3 = (base + 3 < n) ? c[base + 3] : 0;
    int s = v0 + v1 + v2 + v3;
    int x = s;
#pragma unroll
    for (int d = 1; d < 32; d <<= 1) {
        int y = __shfl_up_sync(~0u, x, d);
        if (lane >= d) x += y;
    }
    if (lane == 31) wsum[wid] = x;
    __syncthreads();
    if (wid == 0) {
        int w = wsum[lane];
#pragma unroll
        for (int d = 1; d < 32; d <<= 1) {
            int y = __shfl_up_sync(~0u, w, d);
            if (lane >= d) w += y;
        }
        wsum[lane] = w;
    }
    __syncthreads();
    int run = x - s + (wid ? wsum[wid - 1] : 0);
    if (base     < n) o[base]     = run; run += v0;
    if (base + 1 < n) o[base + 1] = run; run += v1;
    if (base + 2 < n) o[base + 2] = run; run += v2;
    if (base + 3 < n) o[base + 3] = run;
    if (tid == 0) bsum[conv * 64 + blockIdx.x] = wsum[31];
}

__global__ void scan_phase2(int* __restrict__ bsum, int na, int nb_, int nc,
                            int* __restrict__ off) {
    __shared__ int tmp[64];
    int conv = blockIdx.x;
    int n = (conv == 0) ? na : (conv == 1) ? nb_ : nc;
    int base0 = (conv == 0) ? OFF0 : (conv == 1) ? OFF1 : OFF2;
    int* bs = bsum + conv * 64;
    int nb = (n + 4095) / 4096;
    int tid = threadIdx.x;
    int v = (tid < nb) ? bs[tid] : 0;
    tmp[tid] = v;
    __syncthreads();
    int x = v;
    for (int d = 1; d < 64; d <<= 1) {
        int y = (tid >= d) ? tmp[tid - d] : 0;
        __syncthreads();
        x += y;
        tmp[tid] = x;
        __syncthreads();
    }
    if (tid < nb) bs[tid] = x - v;
    if (tid == 63) off[base0 + n] = x;
}

__global__ void scan_phase3(int* __restrict__ off, const int* __restrict__ bsum,
                            int na, int nb_, int nc, int* __restrict__ cur) {
    int conv = blockIdx.y;
    int n = (conv == 0) ? na : (conv == 1) ? nb_ : nc;
    int i = blockIdx.x * blockDim.x + threadIdx.x;
    if (i >= n) return;
    int base0 = (conv == 0) ? OFF0 : (conv == 1) ? OFF1 : OFF2;
    int o = off[base0 + i] + bsum[conv * 64 + (i >> 12)];
    off[base0 + i] = o;
    cur[base0 + i] = o;
}

__global__ void fill_all_kernel(const int* __restrict__ e0, int n0,
                                const int* __restrict__ e1, int n1,
                                const int* __restrict__ e2, int n2,
                                int* __restrict__ cur, int* __restrict__ col) {
    int i = blockIdx.x * blockDim.x + threadIdx.x;
    const int* idx; int j, np, base0, cbase;
    if (i < n0)                { idx = e0; j = i;           np = n0; base0 = OFF0; cbase = 0; }
    else if (i < n0 + n1)      { idx = e1; j = i - n0;      np = n1; base0 = OFF1; cbase = n0; }
    else if (i < n0 + n1 + n2) { idx = e2; j = i - n0 - n1; np = n2; base0 = OFF2; cbase = n0 + n1; }
    else return;
    int d = idx[j];
    int s = idx[j + np];
    int pos = atomicAdd(&cur[base0 + d], 1);
    col[cbase + pos] = s;
}

// ---------- fused segment-min (fp16) + (x_dst - min) -> fp16, degree-specialized ----------
__global__ void segmin_csr_kernel(const int* __restrict__ off, const int* __restrict__ col,
                                  int n_dst,
                                  const __half* __restrict__ xsrc16,
                                  const __half* __restrict__ xdst16,
                                  __half* __restrict__ mh16) {
    int w = (blockIdx.x * blockDim.x + threadIdx.x) >> 5;
    int lane = threadIdx.x & 31;
    if (w >= n_dst) return;
    int beg = off[w], end = off[w + 1];
    int deg = end - beg;
    uint4 outv;
    __half2* oh = reinterpret_cast<__half2*>(&outv);

    if (deg <= 0) {
        outv = make_uint4(0, 0, 0, 0);
    } else {
        __half2 m[4];
        if (deg == 1) {
            int c0 = col[beg];
            uint4 v0 = reinterpret_cast<const uint4*>(xsrc16 + (size_t)c0 * H)[lane];
            const __half2* h0 = reinterpret_cast<const __half2*>(&v0);
#pragma unroll
            for (int q = 0; q < 4; q++) m[q] = h0[q];
        } else if (deg == 2) {
            int c0 = col[beg], c1 = col[beg + 1];
            uint4 v0 = reinterpret_cast<const uint4*>(xsrc16 + (size_t)c0 * H)[lane];
            uint4 v1 = reinterpret_cast<const uint4*>(xsrc16 + (size_t)c1 * H)[lane];
            const __half2* h0 = reinterpret_cast<const __half2*>(&v0);
            const __half2* h1 = reinterpret_cast<const __half2*>(&v1);
#pragma unroll
            for (int q = 0; q < 4; q++) m[q] = __hmin2(h0[q], h1[q]);
        } else {
            const __half2 inf2 = __halves2half2(__ushort_as_half(0x7C00), __ushort_as_half(0x7C00));
#pragma unroll
            for (int q = 0; q < 4; q++) m[q] = inf2;
            for (int j = beg; j < end; j += 4) {
                int c0 = col[j];
                int c1 = (j + 1 < end) ? col[j + 1] : c0;
                int c2 = (j + 2 < end) ? col[j + 2] : c0;
                int c3 = (j + 3 < end) ? col[j + 3] : c0;
                uint4 v0 = reinterpret_cast<const uint4*>(xsrc16 + (size_t)c0 * H)[lane];
                uint4 v1 = reinterpret_cast<const uint4*>(xsrc16 + (size_t)c1 * H)[lane];
                uint4 v2 = reinterpret_cast<const uint4*>(xsrc16 + (size_t)c2 * H)[lane];
                uint4 v3 = reinterpret_cast<const uint4*>(xsrc16 + (size_t)c3 * H)[lane];
                const __half2* h0 = reinterpret_cast<const __half2*>(&v0);
                const __half2* h1 = reinterpret_cast<const __half2*>(&v1);
                const __half2* h2 = reinterpret_cast<const __half2*>(&v2);
                const __half2* h3 = reinterpret_cast<const __half2*>(&v3);
#pragma unroll
                for (int q = 0; q < 4; q++) {
                    __half2 a = __hmin2(h0[q], h1[q]);
                    __half2 b = __hmin2(h2[q], h3[q]);
                    m[q] = __hmin2(m[q], __hmin2(a, b));
                }
            }
        }
        uint4 xd = reinterpret_cast<const uint4*>(xdst16 + (size_t)w * H)[lane];
        const __half2* hx = reinterpret_cast<const __half2*>(&xd);
#pragma unroll
        for (int q = 0; q < 4; q++) oh[q] = __hsub2(hx[q], m[q]);
    }
    reinterpret_cast<uint4*>(mh16 + (size_t)w * H)[lane] = outv;
}

// ---------- fp16 tensor-core conv GEMM: 128x256 tile, 16 warps, ldmatrix, 4-stage ----------
#define BM 128
#define BK 32
#define RSTR 20                     // row stride in 32-bit words (16 used + 4 pad)
#define A_WORDS (128 * RSTR)        // 2560
#define B_WORDS (256 * RSTR)        // 5120
#define STG_WORDS (A_WORDS + B_WORDS)
#define STG_BYTES (STG_WORDS * 4)   // 30720
#define GEMM_SMEM (4 * STG_BYTES)   // 122880

__global__ __launch_bounds__(512, 1) void conv_gemm_fp16(const __half* __restrict__ x16,
                                                         const __half* __restrict__ mh16,
                                                         const __half* __restrict__ Wt16,
                                                         const float* __restrict__ bias,
                                                         float* __restrict__ out32,
                                                         __half* __restrict__ out16, int M) {
    extern __shared__ unsigned sm[];
    int tid = threadIdx.x;
    int warp = tid >> 5, lane = tid & 31;
    int g = lane >> 2, t = lane & 3;
    int wr = warp >> 2, wc = warp & 3;       // 4x4 warp grid
    int m_w = wr * 32, n_w = wc * 64;        // warp tile 32x64
    int bm = blockIdx.x * BM;

    int prow = tid >> 2;                     // 0..127
    int pc = tid & 3;

    float c[2][8][4];
#pragma unroll
    for (int i = 0; i < 2; i++)
#pragma unroll
        for (int j = 0; j < 8; j++)
#pragma unroll
            for (int q = 0; q < 4; q++) c[i][j][q] = 0.f;

    auto prefetch = [&](int tile, int slot) {
        int k0 = tile * BK;
        const __half* Ab = (k0 < 256) ? x16 : mh16;
        int kk = k0 & 255;
        unsigned* Ad = sm + slot * STG_WORDS;
        unsigned* Bd = Ad + A_WORDS;
        {
            bool v = (bm + prow) < M;
            const __half* gp = Ab + (size_t)(v ? bm + prow : 0) * H + kk + pc * 8;
            cp16(Ad + prow * RSTR + pc * 4, gp, v);
        }
#pragma unroll
        for (int r = 0; r < 2; r++) {
            int row = prow + r * 128;
            cp16(Bd + row * RSTR + pc * 4,
                 Wt16 + (size_t)row * 512 + k0 + pc * 8, true);
        }
        cp_commit();
    };

    prefetch(0, 0);
    prefetch(1, 1);
    prefetch(2, 2);

    unsigned sb = (unsigned)__cvta_generic_to_shared(sm);
    unsigned aOff = (unsigned)((m_w + (lane & 15)) * RSTR) * 4 + (unsigned)(lane >> 4) * 16;
    unsigned bOff = (unsigned)A_WORDS * 4 +
                    (unsigned)((n_w + (lane & 7) + ((lane >> 4) << 3)) * RSTR) * 4 +
                    (unsigned)((lane >> 3) & 1) * 16;

    for (int it = 0; it < 16; it++) {
        if (it <= 13) cp_wait<2>();
        else if (it == 14) cp_wait<1>();
        else cp_wait<0>();
        __syncthreads();

        int slot = it & 3;
        unsigned aBase = sb + slot * STG_BYTES + aOff;
        unsigned bBase = sb + slot * STG_BYTES + bOff;
#pragma unroll
        for (int ks = 0; ks < 2; ks++) {
            unsigned kB = ks * 32;
            unsigned a[2][4], b[8][2];
#pragma unroll
            for (int i = 0; i < 2; i++)
                ldsm_x4(a[i][0], a[i][1], a[i][2], a[i][3], aBase + i * (16 * RSTR * 4) + kB);
#pragma unroll
            for (int jj = 0; jj < 4; jj++)
                ldsm_x4(b[2 * jj][0], b[2 * jj][1], b[2 * jj + 1][0], b[2 * jj + 1][1],
                        bBase + jj * (16 * RSTR * 4) + kB);
#pragma unroll
            for (int i = 0; i < 2; i++)
#pragma unroll
                for (int j = 0; j < 8; j++) mma_fp16(c[i][j], a[i], b[j]);
        }

        if (it + 3 <= 15) prefetch(it + 3, (it + 3) & 3);
    }

    // epilogue: out = x16 + leaky(c + bias)
#pragma unroll
    for (int i = 0; i < 2; i++) {
        int r0 = bm + m_w + i * 16 + g;
        int r1 = r0 + 8;
#pragma unroll
        for (int j = 0; j < 8; j++) {
            int col = n_w + j * 8 + t * 2;
            float b0 = bias[col], b1 = bias[col + 1];
            if (r0 < M) {
                size_t o = (size_t)r0 * H + col;
                float2 xf = __half22float2(*reinterpret_cast<const __half2*>(x16 + o));
                float v0 = xf.x + leaky(c[i][j][0] + b0);
                float v1 = xf.y + leaky(c[i][j][1] + b1);
                if (out32) { out32[o] = v0; out32[o + 1] = v1; }
                if (out16) *reinterpret_cast<__half2*>(out16 + o) = __floats2half2_rn(v0, v1);
            }
            if (r1 < M) {
                size_t o = (size_t)r1 * H + col;
                float2 xf = __half22float2(*reinterpret_cast<const __half2*>(x16 + o));
                float v0 = xf.x + leaky(c[i][j][2] + b0);
                float v1 = xf.y + leaky(c[i][j][3] + b1);
                if (out32) { out32[o] = v0; out32[o + 1] = v1; }
                if (out16) *reinterpret_cast<__half2*>(out16 + o) = __floats2half2_rn(v0, v1);
            }
        }
    }
}

// ---------- launch ----------
static inline int cdiv(int a, int b) { return (a + b - 1) / b; }

extern "C" void kernel_launch(void* const* d_in, const int* in_sizes, int n_in,
                              void* d_out, int out_size) {
    const float* vp  = (const float*)d_in[0];
    const float* ec  = (const float*)d_in[1];
    const float* ecp = (const float*)d_in[2];
    const float* ecf = (const float*)d_in[3];
    const float* lt  = (const float*)d_in[4];
    const float* fs  = (const float*)d_in[5];
    const float* fsp = (const float*)d_in[6];
    const float* fsf = (const float*)d_in[7];
    const int* ev = (const int*)d_in[8];
    const int* le = (const int*)d_in[9];
    const int* fl = (const int*)d_in[10];
    const float* Wv = (const float*)d_in[11]; const float* bv = (const float*)d_in[12];
    const float* We = (const float*)d_in[13]; const float* be = (const float*)d_in[14];
    const float* Wl = (const float*)d_in[15]; const float* bl = (const float*)d_in[16];
    const float* Wf = (const float*)d_in[17]; const float* bf = (const float*)d_in[18];
    const float* Wve = (const float*)d_in[19]; const float* bve = (const float*)d_in[20];
    const float* Wel = (const float*)d_in[21]; const float* bel = (const float*)d_in[22];
    const float* Wlf = (const float*)d_in[23]; const float* blf = (const float*)d_in[24];

    int NVn = in_sizes[0] / 3;
    int NEn = in_sizes[1] / 8;
    int NLn = in_sizes[4] / 10;
    int NFn = in_sizes[5] / 12;
    int nEV = in_sizes[8] / 2;
    int nLE = in_sizes[9] / 2;
    int nFL = in_sizes[10] / 2;

    __half *pv16, *pe16, *peo16, *pl16, *pf16, *pmh16, *pwt16;
    int *pcnt, *poff, *pcur, *pcol, *pbsum;
    cudaGetSymbolAddress((void**)&pv16,  g_v16);
    cudaGetSymbolAddress((void**)&pe16,  g_e16);
    cudaGetSymbolAddress((void**)&peo16, g_eo16);
    cudaGetSymbolAddress((void**)&pl16,  g_l16);
    cudaGetSymbolAddress((void**)&pf16,  g_f16);
    cudaGetSymbolAddress((void**)&pmh16, g_mh16);
    cudaGetSymbolAddress((void**)&pwt16, g_wt16);
    cudaGetSymbolAddress((void**)&pcnt,  g_cnt);
    cudaGetSymbolAddress((void**)&poff,  g_off);
    cudaGetSymbolAddress((void**)&pcur,  g_cur);
    cudaGetSymbolAddress((void**)&pcol,  g_col);
    cudaGetSymbolAddress((void**)&pbsum, g_bsum);

    cudaFuncSetAttribute(conv_gemm_fp16, cudaFuncAttributeMaxDynamicSharedMemorySize, GEMM_SMEM);

    int nPairTot = nEV + nLE + nFL;
    int nmax = NEn;

    // merged prep: weight transposes + degree counts (after memset)
    cudaMemsetAsync(pcnt, 0, (size_t)CSRTOT * sizeof(int));
    prep_kernel<<<384 + cdiv(nPairTot, 256), 256>>>(Wve, Wel, Wlf, pwt16,
                                                    ev, nEV, le, nLE, fl, nFL, pcnt);
    {
        dim3 g1(cdiv(nmax, 4096), 3);
        scan_phase1<<<g1, 1024>>>(pcnt, NEn, NLn, NFn, poff, pbsum);
        scan_phase2<<<3, 64>>>(pbsum, NEn, NLn, NFn, poff);
        dim3 g3(cdiv(nmax, 256), 3);
        scan_phase3<<<g3, 256>>>(poff, pbsum, NEn, NLn, NFn, pcur);
    }
    fill_all_kernel<<<cdiv(nPairTot, 256), 256>>>(ev, nEV, le, nLE, fl, nFL, pcur, pcol);

    // embeddings: all four in one launch, fp16 outputs only
    {
        int nbv = cdiv(NVn, 32), nbe = cdiv(NEn, 32), nbl = cdiv(NLn, 32), nbf = cdiv(NFn, 32);
        embed_all<<<nbv + nbe + nbl + nbf, 256>>>(vp, ec, ecp, ecf, lt, fs, fsp, fsf,
                                                  Wv, bv, We, be, Wl, bl, Wf, bf,
                                                  pv16, pe16, pl16, pf16,
                                                  NVn, NEn, NLn, NFn, nbv, nbe, nbl);
    }

    // conv 1: vertices -> edges
    segmin_csr_kernel<<<cdiv(NEn * 32, 256), 256>>>(poff + OFF0, pcol, NEn, pv16, pe16, pmh16);
    conv_gemm_fp16<<<cdiv(NEn, BM), 512, GEMM_SMEM>>>(pe16, pmh16, pwt16, bve, nullptr, peo16, NEn);

    // conv 2: edges -> loops (fp16 out reuses g_v16)
    segmin_csr_kernel<<<cdiv(NLn * 32, 256), 256>>>(poff + OFF1, pcol + nEV, NLn, peo16, pl16, pmh16);
    conv_gemm_fp16<<<cdiv(NLn, BM), 512, GEMM_SMEM>>>(pl16, pmh16, pwt16 + 512 * 256, bel, nullptr, pv16, NLn);

    // conv 3: loops -> faces (fp32 output = d_out)
    segmin_csr_kernel<<<cdiv(NFn * 32, 256), 256>>>(poff + OFF2, pcol + nEV + nLE, NFn, pv16, pf16, pmh16);
    conv_gemm_fp16<<<cdiv(NFn, BM), 512, GEMM_SMEM>>>(pf16, pmh16, pwt16 + 2 * 512 * 256, blf, (float*)d_out, nullptr, NFn);
}